// round 1
// baseline (speedup 1.0000x reference)
#include <cuda_runtime.h>
#include <cuda_bf16.h>

// Problem constants
#define M_DIM   128
#define D_DIM   16
#define W_DIM   15
#define POS     (W_DIM * W_DIM * W_DIM * W_DIM)   // 50625
#define BATCH   4
#define ROWS    (BATCH * POS)                      // 202500

// Scratch (allocation-free rule: __device__ globals)
__device__ float g_pooled[(size_t)ROWS * M_DIM];   // ~104 MB
__device__ float g_nk[256 * M_DIM];                // 128 KB: Nk table over the 256 distinct idx values

// ---------------------------------------------------------------------------
// Nk table: g_nk[idx][j] = Acoeff[j][idx] * Bbasis[idx][j]
// Acoeff: (128, 256) row-major; Bbasis: (256, 128) row-major
// ---------------------------------------------------------------------------
__global__ void nk_kernel(const float* __restrict__ Acoeff,
                          const float* __restrict__ Bbasis) {
    int idx = blockIdx.x;     // 0..255
    int j   = threadIdx.x;    // 0..127
    g_nk[idx * M_DIM + j] = Acoeff[j * 256 + idx] * Bbasis[idx * M_DIM + j];
}

// ---------------------------------------------------------------------------
// Pooling: pooled[b, k1..k4, :] = mean over 2x2x2x2 window of vec_arr
// One float4 (4 channels) per thread; 16 LDG.128 with strong L1 locality.
// ---------------------------------------------------------------------------
__global__ void pool_kernel(const float4* __restrict__ vec) {
    long long tid = (long long)blockIdx.x * blockDim.x + threadIdx.x;
    const long long total = (long long)ROWS * (M_DIM / 4);
    if (tid >= total) return;

    int row = (int)(tid >> 5);        // pooled row (b*POS + pos)
    int q   = (int)(tid & 31);        // float4 index within the 128 channels

    int b   = row / POS;
    int pos = row - b * POS;
    int k4  = pos % W_DIM;
    int r1  = pos / W_DIM;
    int k3  = r1 % W_DIM;
    int r2  = r1 / W_DIM;
    int k2  = r2 % W_DIM;
    int k1  = r2 / W_DIM;

    // strides in float4 units (channel dim = 32 float4s)
    const int S4 = 32;
    const int S3 = 32 * D_DIM;             // 512
    const int S2 = 32 * D_DIM * D_DIM;     // 8192
    const int S1 = 32 * D_DIM * D_DIM * D_DIM; // 131072
    const long long SB = (long long)S1 * D_DIM;

    const float4* base = vec + (long long)b * SB
                             + (long long)k1 * S1 + (long long)k2 * S2
                             + (long long)k3 * S3 + (long long)k4 * S4 + q;

    float sx = 0.f, sy = 0.f, sz = 0.f, sw = 0.f;
#pragma unroll
    for (int a = 0; a < 2; a++)
#pragma unroll
        for (int c = 0; c < 2; c++)
#pragma unroll
            for (int d = 0; d < 2; d++)
#pragma unroll
                for (int e = 0; e < 2; e++) {
                    float4 v = base[a * S1 + c * S2 + d * S3 + e * S4];
                    sx += v.x; sy += v.y; sz += v.z; sw += v.w;
                }

    float4 o;
    o.x = sx * 0.0625f; o.y = sy * 0.0625f; o.z = sz * 0.0625f; o.w = sw * 0.0625f;
    ((float4*)g_pooled)[tid] = o;
}

// ---------------------------------------------------------------------------
// GEMM + epilogue: out[row][j] = g_nk[idx(row)][j] - sum_i pooled[row][i]*M[j][i]
// Tile: 64 rows x 128 cols per block, 256 threads, 8x4 register microtile.
// Mt in smem with row stride 132 floats (16B-aligned, conflict-free LDS.128).
// ---------------------------------------------------------------------------
#define MT_STRIDE 132
#define GEMM_SMEM_BYTES ((M_DIM * MT_STRIDE + 64 * M_DIM) * 4)

__global__ void __launch_bounds__(256, 2)
gemm_kernel(const float* __restrict__ Mmat, float* __restrict__ out) {
    extern __shared__ float sm[];
    float* Mt = sm;                       // [128][132]: Mt[i][j] = M[j][i]
    float* P  = sm + M_DIM * MT_STRIDE;   // [64][128]

    const int t = threadIdx.x;
    const int row0 = blockIdx.x * 64;

    // Load & transpose M (coalesced gmem read)
#pragma unroll
    for (int e = t; e < M_DIM * M_DIM; e += 256) {
        int j = e >> 7, i = e & 127;
        Mt[i * MT_STRIDE + j] = Mmat[e];
    }
    // Load pooled tile
#pragma unroll
    for (int e = t; e < 64 * M_DIM; e += 256) {
        int r = e >> 7, c = e & 127;
        int row = row0 + r;
        P[e] = (row < ROWS) ? g_pooled[(long long)row * M_DIM + c] : 0.f;
    }
    __syncthreads();

    const int tc = t & 31;   // lane -> column group (cols tc*4 .. tc*4+3)
    const int tr = t >> 5;   // warp -> row group (rows tr*8 .. tr*8+7)

    float acc[8][4];
#pragma unroll
    for (int r = 0; r < 8; r++)
#pragma unroll
        for (int c = 0; c < 4; c++) acc[r][c] = 0.f;

    for (int k = 0; k < M_DIM; k += 4) {
        float4 bv[4];
#pragma unroll
        for (int kk = 0; kk < 4; kk++)
            bv[kk] = *(const float4*)&Mt[(k + kk) * MT_STRIDE + tc * 4];
        float4 av[8];
#pragma unroll
        for (int r = 0; r < 8; r++)
            av[r] = *(const float4*)&P[(tr * 8 + r) * M_DIM + k];
#pragma unroll
        for (int r = 0; r < 8; r++) {
#pragma unroll
            for (int c = 0; c < 4; c++) {
                float bk0 = (c == 0) ? bv[0].x : (c == 1) ? bv[0].y : (c == 2) ? bv[0].z : bv[0].w;
                float bk1 = (c == 0) ? bv[1].x : (c == 1) ? bv[1].y : (c == 2) ? bv[1].z : bv[1].w;
                float bk2 = (c == 0) ? bv[2].x : (c == 1) ? bv[2].y : (c == 2) ? bv[2].z : bv[2].w;
                float bk3 = (c == 0) ? bv[3].x : (c == 1) ? bv[3].y : (c == 2) ? bv[3].z : bv[3].w;
                acc[r][c] += av[r].x * bk0;
                acc[r][c] += av[r].y * bk1;
                acc[r][c] += av[r].z * bk2;
                acc[r][c] += av[r].w * bk3;
            }
        }
    }

    // Epilogue: out = Nk - acc
#pragma unroll
    for (int r = 0; r < 8; r++) {
        int row = row0 + tr * 8 + r;
        if (row >= ROWS) continue;
        int pos = row % POS;
        int k4 = pos % W_DIM;
        int q1 = pos / W_DIM;
        int k3 = q1 % W_DIM;
        int q2 = q1 / W_DIM;
        int k2 = q2 % W_DIM;
        int k1 = q2 / W_DIM;
        int idx = (((k1 & 3) * 4 + (k2 & 3)) * 4 + (k3 & 3)) * 4 + (k4 & 3);
        float4 nk = *(const float4*)&g_nk[idx * M_DIM + tc * 4];
        float4 o;
        o.x = nk.x - acc[r][0];
        o.y = nk.y - acc[r][1];
        o.z = nk.z - acc[r][2];
        o.w = nk.w - acc[r][3];
        *(float4*)&out[(long long)row * M_DIM + tc * 4] = o;
    }
}

// ---------------------------------------------------------------------------
extern "C" void kernel_launch(void* const* d_in, const int* in_sizes, int n_in,
                              void* d_out, int out_size) {
    const float* vec    = (const float*)d_in[0];   // (4,16,16,16,16,128)
    const float* Mmat   = (const float*)d_in[1];   // (128,128)
    const float* Acoeff = (const float*)d_in[2];   // (128,256)
    const float* Bbasis = (const float*)d_in[3];   // (256,128)
    float* out = (float*)d_out;                    // (4, 50625, 128)

    static bool attr_set_done = false;
    // Setting the attribute is idempotent and executes immediately (not a
    // stream op), so it is graph-capture safe; call unconditionally.
    cudaFuncSetAttribute(gemm_kernel,
                         cudaFuncAttributeMaxDynamicSharedMemorySize,
                         GEMM_SMEM_BYTES);
    (void)attr_set_done;

    // 1) Nk table (256 idx values x 128 channels)
    nk_kernel<<<256, 128>>>(Acoeff, Bbasis);

    // 2) Pooling
    {
        long long total = (long long)ROWS * (M_DIM / 4);
        int blocks = (int)((total + 255) / 256);
        pool_kernel<<<blocks, 256>>>((const float4*)vec);
    }

    // 3) GEMM + epilogue
    {
        int blocks = (ROWS + 63) / 64;   // 3165
        gemm_kernel<<<blocks, 256, GEMM_SMEM_BYTES>>>(Mmat, out);
    }
}

// round 3
// speedup vs baseline: 1.2059x; 1.2059x over previous
#include <cuda_runtime.h>
#include <cuda_bf16.h>
#include <cstdint>

#define M_DIM 128
#define D_DIM 16
#define W_DIM 15
#define POS   (W_DIM*W_DIM*W_DIM*W_DIM)   // 50625
#define BATCH 4
#define ROWS  (BATCH*POS)                  // 202500
#define TILES ((ROWS + 127) / 128)         // 1583

// Nk table over the 256 distinct basis indices (allocation-free scratch)
__device__ float g_nk[256 * M_DIM];

// ---------------------------------------------------------------------------
// Nk table: g_nk[idx][j] = Acoeff[j][idx] * Bbasis[idx][j]
// ---------------------------------------------------------------------------
__global__ void nk_kernel(const float* __restrict__ Acoeff,
                          const float* __restrict__ Bbasis) {
    int e = blockIdx.x * blockDim.x + threadIdx.x;  // 0..32767
    int idx = e >> 7, j = e & 127;
    g_nk[e] = Acoeff[j * 256 + idx] * Bbasis[idx * M_DIM + j];
}

// ---------------------------------------------------------------------------
// bf16 helpers
// ---------------------------------------------------------------------------
__device__ __forceinline__ uint32_t pack_bf16(__nv_bfloat16 a, __nv_bfloat16 b) {
    return ((uint32_t)__bfloat16_as_ushort(b) << 16) | __bfloat16_as_ushort(a);
}
__device__ __forceinline__ void split2(float x, float y, uint32_t& hi, uint32_t& lo) {
    __nv_bfloat16 hx = __float2bfloat16_rn(x);
    __nv_bfloat16 hy = __float2bfloat16_rn(y);
    __nv_bfloat16 lx = __float2bfloat16_rn(x - __bfloat162float(hx));
    __nv_bfloat16 ly = __float2bfloat16_rn(y - __bfloat162float(hy));
    hi = pack_bf16(hx, hy);
    lo = pack_bf16(lx, ly);
}

// m16n8k16 row.col f32.bf16.bf16.f32 (HMMA on tensor pipe; base-target PTX)
__device__ __forceinline__ void mma_bf16(float* c, const uint32_t* a, const uint32_t* b) {
    asm volatile(
        "mma.sync.aligned.m16n8k16.row.col.f32.bf16.bf16.f32 "
        "{%0,%1,%2,%3}, {%4,%5,%6,%7}, {%8,%9}, {%0,%1,%2,%3};"
        : "+f"(c[0]), "+f"(c[1]), "+f"(c[2]), "+f"(c[3])
        : "r"(a[0]), "r"(a[1]), "r"(a[2]), "r"(a[3]), "r"(b[0]), "r"(b[1]));
}

// ---------------------------------------------------------------------------
// SMEM layout: A_hi/A_lo: [128 rows][128 k] bf16, pitch 136 bf16 (272B)
//              B_hi/B_lo: [128 n][128 k]  bf16, same pitch  (B[n][k] = M[n][k])
// pitch 272B = 68 words; 68 mod 32 = 4 -> 8 consecutive rows hit banks
// {4r + lane%4}: conflict-free 4B fragment loads.
// ---------------------------------------------------------------------------
#define PITCH_B   272
#define TILE_B    (128 * PITCH_B)          // 34816
#define OFF_A_HI  0
#define OFF_A_LO  (TILE_B)
#define OFF_B_HI  (2 * TILE_B)
#define OFF_B_LO  (3 * TILE_B)
#define SMEM_TOTAL (4 * TILE_B)            // 139264

__global__ void __launch_bounds__(256, 1)
fused_kernel(const float4* __restrict__ vec, const float4* __restrict__ Mmat,
             float* __restrict__ out) {
    extern __shared__ char smem[];
    const int t    = threadIdx.x;
    const int wid  = t >> 5;
    const int lane = t & 31;
    const int row0 = blockIdx.x * 128;

    // ---- B tiles: M (fp32, L2-hot) -> bf16 hi/lo ----
#pragma unroll
    for (int e = t; e < 4096; e += 256) {            // 128 n-rows x 32 float4
        int n = e >> 5, kq = e & 31;
        float4 v = __ldg(&Mmat[e]);
        uint2 hv, lv;
        split2(v.x, v.y, hv.x, lv.x);
        split2(v.z, v.w, hv.y, lv.y);
        uint32_t off = (uint32_t)(n * PITCH_B + kq * 8);
        *(uint2*)(smem + OFF_B_HI + off) = hv;
        *(uint2*)(smem + OFF_B_LO + off) = lv;
    }

    // ---- A tiles: fused 2x2x2x2 mean pool -> bf16 hi/lo ----
    {
        const int S4 = 32, S3 = 32 * D_DIM, S2 = 32 * D_DIM * D_DIM;
        const int S1 = 32 * D_DIM * D_DIM * D_DIM;
        const long long SB = (long long)S1 * D_DIM;
#pragma unroll
        for (int task = t; task < 4096; task += 256) {  // 128 rows x 32 f4-chunks
            int r = task >> 5, q = task & 31;
            int row = row0 + r;
            float4 o = make_float4(0.f, 0.f, 0.f, 0.f);
            if (row < ROWS) {
                int b   = row / POS;
                int pos = row - b * POS;
                int k4  = pos % W_DIM;
                int r1  = pos / W_DIM;
                int k3  = r1 % W_DIM;
                int r2  = r1 / W_DIM;
                int k2  = r2 % W_DIM;
                int k1  = r2 / W_DIM;
                const float4* base = vec + (long long)b * SB
                    + (long long)k1 * S1 + (long long)k2 * S2
                    + (long long)k3 * S3 + (long long)k4 * S4 + q;
                float sx = 0.f, sy = 0.f, sz = 0.f, sw = 0.f;
#pragma unroll
                for (int a = 0; a < 2; a++)
#pragma unroll
                    for (int c = 0; c < 2; c++)
#pragma unroll
                        for (int d = 0; d < 2; d++)
#pragma unroll
                            for (int e2 = 0; e2 < 2; e2++) {
                                float4 v = base[a * S1 + c * S2 + d * S3 + e2 * S4];
                                sx += v.x; sy += v.y; sz += v.z; sw += v.w;
                            }
                o.x = sx * 0.0625f; o.y = sy * 0.0625f;
                o.z = sz * 0.0625f; o.w = sw * 0.0625f;
            }
            uint2 hv, lv;
            split2(o.x, o.y, hv.x, lv.x);
            split2(o.z, o.w, hv.y, lv.y);
            uint32_t off = (uint32_t)(r * PITCH_B + q * 8);
            *(uint2*)(smem + OFF_A_HI + off) = hv;
            *(uint2*)(smem + OFF_A_LO + off) = lv;
        }
    }
    __syncthreads();

    // ---- Mainloop: warp tile 32(m) x 64(n); 3 split passes fused per k-step ----
    const int wm = wid & 3;          // row block (32 rows)
    const int wn = wid >> 2;         // col block (64 cols)
    const int g  = lane >> 2;        // fragment row/col group
    const int qb = (lane & 3) * 4;   // fragment k byte offset

    const char* Ah = smem + OFF_A_HI;
    const char* Al = smem + OFF_A_LO;
    const char* Bh = smem + OFF_B_HI;
    const char* Bl = smem + OFF_B_LO;
    const int aBase = (wm * 32 + g) * PITCH_B;
    const int bBase = (wn * 64 + g) * PITCH_B;

    float acc[2][8][4];
#pragma unroll
    for (int mt = 0; mt < 2; mt++)
#pragma unroll
        for (int nt = 0; nt < 8; nt++)
#pragma unroll
            for (int i = 0; i < 4; i++) acc[mt][nt][i] = 0.f;

#pragma unroll
    for (int ks = 0; ks < 8; ks++) {
        const int kb = ks * 32 + qb;
        uint32_t ah[2][4], al[2][4];
#pragma unroll
        for (int mt = 0; mt < 2; mt++) {
            int base = aBase + mt * 16 * PITCH_B + kb;
            ah[mt][0] = *(const uint32_t*)(Ah + base);
            ah[mt][1] = *(const uint32_t*)(Ah + base + 8 * PITCH_B);
            ah[mt][2] = *(const uint32_t*)(Ah + base + 16);
            ah[mt][3] = *(const uint32_t*)(Ah + base + 8 * PITCH_B + 16);
            al[mt][0] = *(const uint32_t*)(Al + base);
            al[mt][1] = *(const uint32_t*)(Al + base + 8 * PITCH_B);
            al[mt][2] = *(const uint32_t*)(Al + base + 16);
            al[mt][3] = *(const uint32_t*)(Al + base + 8 * PITCH_B + 16);
        }
        uint32_t bh[8][2], bl[8][2];
#pragma unroll
        for (int nt = 0; nt < 8; nt++) {
            int base = bBase + nt * 8 * PITCH_B + kb;
            bh[nt][0] = *(const uint32_t*)(Bh + base);
            bh[nt][1] = *(const uint32_t*)(Bh + base + 16);
            bl[nt][0] = *(const uint32_t*)(Bl + base);
            bl[nt][1] = *(const uint32_t*)(Bl + base + 16);
        }
#pragma unroll
        for (int mt = 0; mt < 2; mt++)
#pragma unroll
            for (int nt = 0; nt < 8; nt++) {
                mma_bf16(acc[mt][nt], ah[mt], bh[nt]);   // hi*hi
                mma_bf16(acc[mt][nt], al[mt], bh[nt]);   // lo*hi
                mma_bf16(acc[mt][nt], ah[mt], bl[nt]);   // hi*lo
            }
    }

    // ---- Epilogue: out[row][col] = Nk[idx(row)][col] - acc ----
    // acc[mt][nt][{0,1}] -> row = wm*32 + mt*16 + g,      cols c0,c0+1
    // acc[mt][nt][{2,3}] -> row = wm*32 + mt*16 + g + 8,  same cols
    const int cq = (lane & 3) * 2;
#pragma unroll
    for (int mt = 0; mt < 2; mt++) {
#pragma unroll
        for (int half = 0; half < 2; half++) {
            int row = row0 + wm * 32 + mt * 16 + g + half * 8;
            if (row >= ROWS) continue;
            int pos = row % POS;
            int k4 = pos % W_DIM;
            int q1 = pos / W_DIM;
            int k3 = q1 % W_DIM;
            int q2 = q1 / W_DIM;
            int k2 = q2 % W_DIM;
            int k1 = q2 / W_DIM;
            int idx = (((k1 & 3) * 4 + (k2 & 3)) * 4 + (k3 & 3)) * 4 + (k4 & 3);
            const float* nkrow = g_nk + idx * M_DIM;
            float* orow = out + (long long)row * M_DIM;
#pragma unroll
            for (int nt = 0; nt < 8; nt++) {
                int c0 = wn * 64 + nt * 8 + cq;
                float2 nk = __ldg((const float2*)(nkrow + c0));
                float2 o;
                o.x = nk.x - acc[mt][nt][half * 2 + 0];
                o.y = nk.y - acc[mt][nt][half * 2 + 1];
                *(float2*)(orow + c0) = o;
            }
        }
    }
}

// ---------------------------------------------------------------------------
extern "C" void kernel_launch(void* const* d_in, const int* in_sizes, int n_in,
                              void* d_out, int out_size) {
    const float* vec    = (const float*)d_in[0];   // (4,16,16,16,16,128)
    const float* Mmat   = (const float*)d_in[1];   // (128,128)
    const float* Acoeff = (const float*)d_in[2];   // (128,256)
    const float* Bbasis = (const float*)d_in[3];   // (256,128)
    float* out = (float*)d_out;                    // (4, 50625, 128)

    cudaFuncSetAttribute(fused_kernel,
                         cudaFuncAttributeMaxDynamicSharedMemorySize,
                         SMEM_TOTAL);

    nk_kernel<<<128, 256>>>(Acoeff, Bbasis);
    fused_kernel<<<TILES, 256, SMEM_TOTAL>>>((const float4*)vec,
                                             (const float4*)Mmat, out);
}

// round 4
// speedup vs baseline: 1.3863x; 1.1495x over previous
#include <cuda_runtime.h>
#include <cuda_bf16.h>
#include <cstdint>

#define M_DIM 128
#define D_DIM 16
#define W_DIM 15
#define POS   (W_DIM*W_DIM*W_DIM*W_DIM)   // 50625
#define BATCH 4
#define ROWS  (BATCH*POS)                  // 202500
#define TILE_M 64
#define TILES ((ROWS + TILE_M - 1) / TILE_M)   // 3165

// Nk table over the 256 distinct basis indices (allocation-free scratch)
__device__ float g_nk[256 * M_DIM];

__global__ void nk_kernel(const float* __restrict__ Acoeff,
                          const float* __restrict__ Bbasis) {
    int e = blockIdx.x * blockDim.x + threadIdx.x;  // 0..32767
    int idx = e >> 7, j = e & 127;
    g_nk[e] = Acoeff[j * 256 + idx] * Bbasis[idx * M_DIM + j];
}

// ---------------------------------------------------------------------------
// bf16 helpers
// ---------------------------------------------------------------------------
__device__ __forceinline__ uint32_t pack_bf16(__nv_bfloat16 a, __nv_bfloat16 b) {
    return ((uint32_t)__bfloat16_as_ushort(b) << 16) | __bfloat16_as_ushort(a);
}
__device__ __forceinline__ void split2(float x, float y, uint32_t& hi, uint32_t& lo) {
    __nv_bfloat16 hx = __float2bfloat16_rn(x);
    __nv_bfloat16 hy = __float2bfloat16_rn(y);
    __nv_bfloat16 lx = __float2bfloat16_rn(x - __bfloat162float(hx));
    __nv_bfloat16 ly = __float2bfloat16_rn(y - __bfloat162float(hy));
    hi = pack_bf16(hx, hy);
    lo = pack_bf16(lx, ly);
}

__device__ __forceinline__ void mma_bf16(float* c, const uint32_t* a, const uint32_t* b) {
    asm volatile(
        "mma.sync.aligned.m16n8k16.row.col.f32.bf16.bf16.f32 "
        "{%0,%1,%2,%3}, {%4,%5,%6,%7}, {%8,%9}, {%0,%1,%2,%3};"
        : "+f"(c[0]), "+f"(c[1]), "+f"(c[2]), "+f"(c[3])
        : "r"(a[0]), "r"(a[1]), "r"(a[2]), "r"(a[3]), "r"(b[0]), "r"(b[1]));
}

// ---------------------------------------------------------------------------
// SMEM: A_hi/A_lo [64 rows][128 k] bf16 pitch 272B; B_hi/B_lo [128 n][128 k].
// pitch 272B = 68 words -> rows g=0..7 + (lane&3) words hit banks 4g+q:
// conflict-free fragment loads (also at +16B and +8 rows: 544 % 32 == 0).
// ---------------------------------------------------------------------------
#define PITCH_B   272
#define OFF_A_HI  0
#define OFF_A_LO  (TILE_M * PITCH_B)           // 17408
#define OFF_B_HI  (2 * TILE_M * PITCH_B)       // 34816
#define OFF_B_LO  (OFF_B_HI + 128 * PITCH_B)   // 69632
#define SMEM_TOTAL (OFF_B_LO + 128 * PITCH_B)  // 104448

__global__ void __launch_bounds__(256, 2)
fused_kernel(const float4* __restrict__ vec, const float4* __restrict__ Mmat,
             float* __restrict__ out) {
    extern __shared__ char smem[];
    const int t    = threadIdx.x;
    const int wid  = t >> 5;
    const int lane = t & 31;
    const int row0 = blockIdx.x * TILE_M;

    // ---- B tiles: M (fp32, L2-hot) -> bf16 hi/lo ----
#pragma unroll
    for (int e = t; e < 4096; e += 256) {            // 128 n-rows x 32 float4
        int n = e >> 5, kq = e & 31;
        float4 v = __ldg(&Mmat[e]);
        uint2 hv, lv;
        split2(v.x, v.y, hv.x, lv.x);
        split2(v.z, v.w, hv.y, lv.y);
        uint32_t off = (uint32_t)(n * PITCH_B + kq * 8);
        *(uint2*)(smem + OFF_B_HI + off) = hv;
        *(uint2*)(smem + OFF_B_LO + off) = lv;
    }

    // ---- A tiles: fused 2x2x2x2 mean pool -> bf16 hi/lo ----
    {
        const int S4 = 32, S3 = 32 * D_DIM, S2 = 32 * D_DIM * D_DIM;
        const int S1 = 32 * D_DIM * D_DIM * D_DIM;
        const long long SB = (long long)S1 * D_DIM;
#pragma unroll
        for (int task = t; task < TILE_M * 32; task += 256) {  // 64 rows x 32 f4
            int r = task >> 5, q = task & 31;
            int row = row0 + r;
            float4 o = make_float4(0.f, 0.f, 0.f, 0.f);
            if (row < ROWS) {
                int b   = row / POS;
                int pos = row - b * POS;
                int k4  = pos % W_DIM;
                int r1  = pos / W_DIM;
                int k3  = r1 % W_DIM;
                int r2  = r1 / W_DIM;
                int k2  = r2 % W_DIM;
                int k1  = r2 / W_DIM;
                const float4* base = vec + (long long)b * SB
                    + (long long)k1 * S1 + (long long)k2 * S2
                    + (long long)k3 * S3 + (long long)k4 * S4 + q;
                float sx = 0.f, sy = 0.f, sz = 0.f, sw = 0.f;
#pragma unroll
                for (int a = 0; a < 2; a++)
#pragma unroll
                    for (int c = 0; c < 2; c++)
#pragma unroll
                        for (int d = 0; d < 2; d++)
#pragma unroll
                            for (int e2 = 0; e2 < 2; e2++) {
                                float4 v = base[a * S1 + c * S2 + d * S3 + e2 * S4];
                                sx += v.x; sy += v.y; sz += v.z; sw += v.w;
                            }
                o.x = sx * 0.0625f; o.y = sy * 0.0625f;
                o.z = sz * 0.0625f; o.w = sw * 0.0625f;
            }
            uint2 hv, lv;
            split2(o.x, o.y, hv.x, lv.x);
            split2(o.z, o.w, hv.y, lv.y);
            uint32_t off = (uint32_t)(r * PITCH_B + q * 8);
            *(uint2*)(smem + OFF_A_HI + off) = hv;
            *(uint2*)(smem + OFF_A_LO + off) = lv;
        }
    }
    __syncthreads();

    // ---- Mainloop: warp tile 32(m) x 32(n); 3 split passes per k-step ----
    const int wm = wid & 1;          // row block (32 rows)
    const int wn = wid >> 1;         // col block (32 cols)
    const int g  = lane >> 2;        // fragment row/col group
    const int qb = (lane & 3) * 4;   // fragment k byte offset

    const char* Ah = smem + OFF_A_HI;
    const char* Al = smem + OFF_A_LO;
    const char* Bh = smem + OFF_B_HI;
    const char* Bl = smem + OFF_B_LO;
    const int aBase = (wm * 32 + g) * PITCH_B;
    const int bBase = (wn * 32 + g) * PITCH_B;

    float acc[2][4][4];
#pragma unroll
    for (int mt = 0; mt < 2; mt++)
#pragma unroll
        for (int nt = 0; nt < 4; nt++)
#pragma unroll
            for (int i = 0; i < 4; i++) acc[mt][nt][i] = 0.f;

#pragma unroll
    for (int ks = 0; ks < 8; ks++) {
        const int kb = ks * 32 + qb;
        uint32_t ah[2][4], al[2][4];
#pragma unroll
        for (int mt = 0; mt < 2; mt++) {
            int base = aBase + mt * 16 * PITCH_B + kb;
            ah[mt][0] = *(const uint32_t*)(Ah + base);
            ah[mt][1] = *(const uint32_t*)(Ah + base + 8 * PITCH_B);
            ah[mt][2] = *(const uint32_t*)(Ah + base + 16);
            ah[mt][3] = *(const uint32_t*)(Ah + base + 8 * PITCH_B + 16);
            al[mt][0] = *(const uint32_t*)(Al + base);
            al[mt][1] = *(const uint32_t*)(Al + base + 8 * PITCH_B);
            al[mt][2] = *(const uint32_t*)(Al + base + 16);
            al[mt][3] = *(const uint32_t*)(Al + base + 8 * PITCH_B + 16);
        }
        uint32_t bh[4][2], bl[4][2];
#pragma unroll
        for (int nt = 0; nt < 4; nt++) {
            int base = bBase + nt * 8 * PITCH_B + kb;
            bh[nt][0] = *(const uint32_t*)(Bh + base);
            bh[nt][1] = *(const uint32_t*)(Bh + base + 16);
            bl[nt][0] = *(const uint32_t*)(Bl + base);
            bl[nt][1] = *(const uint32_t*)(Bl + base + 16);
        }
#pragma unroll
        for (int mt = 0; mt < 2; mt++)
#pragma unroll
            for (int nt = 0; nt < 4; nt++) {
                mma_bf16(acc[mt][nt], ah[mt], bh[nt]);   // hi*hi
                mma_bf16(acc[mt][nt], al[mt], bh[nt]);   // lo*hi
                mma_bf16(acc[mt][nt], ah[mt], bl[nt]);   // hi*lo
            }
    }

    // ---- Epilogue: out[row][col] = Nk[idx(row)][col] - acc ----
    const int cq = (lane & 3) * 2;
#pragma unroll
    for (int mt = 0; mt < 2; mt++) {
#pragma unroll
        for (int half = 0; half < 2; half++) {
            int row = row0 + wm * 32 + mt * 16 + g + half * 8;
            if (row >= ROWS) continue;
            int pos = row % POS;
            int k4 = pos % W_DIM;
            int q1 = pos / W_DIM;
            int k3 = q1 % W_DIM;
            int q2 = q1 / W_DIM;
            int k2 = q2 % W_DIM;
            int k1 = q2 / W_DIM;
            int idx = (((k1 & 3) * 4 + (k2 & 3)) * 4 + (k3 & 3)) * 4 + (k4 & 3);
            const float* nkrow = g_nk + idx * M_DIM;
            float* orow = out + (long long)row * M_DIM;
#pragma unroll
            for (int nt = 0; nt < 4; nt++) {
                int c0 = wn * 32 + nt * 8 + cq;
                float2 nk = __ldg((const float2*)(nkrow + c0));
                float2 o;
                o.x = nk.x - acc[mt][nt][half * 2 + 0];
                o.y = nk.y - acc[mt][nt][half * 2 + 1];
                *(float2*)(orow + c0) = o;
            }
        }
    }
}

// ---------------------------------------------------------------------------
extern "C" void kernel_launch(void* const* d_in, const int* in_sizes, int n_in,
                              void* d_out, int out_size) {
    const float* vec    = (const float*)d_in[0];   // (4,16,16,16,16,128)
    const float* Mmat   = (const float*)d_in[1];   // (128,128)
    const float* Acoeff = (const float*)d_in[2];   // (128,256)
    const float* Bbasis = (const float*)d_in[3];   // (256,128)
    float* out = (float*)d_out;                    // (4, 50625, 128)

    cudaFuncSetAttribute(fused_kernel,
                         cudaFuncAttributeMaxDynamicSharedMemorySize,
                         SMEM_TOTAL);

    nk_kernel<<<128, 256>>>(Acoeff, Bbasis);
    fused_kernel<<<TILES, 256, SMEM_TOTAL>>>((const float4*)vec,
                                             (const float4*)Mmat, out);
}

// round 5
// speedup vs baseline: 1.5150x; 1.0928x over previous
#include <cuda_runtime.h>
#include <cuda_bf16.h>
#include <cstdint>

#define M_DIM 128
#define D_DIM 16
#define W_DIM 15
#define POS   (W_DIM*W_DIM*W_DIM*W_DIM)   // 50625
#define BATCH 4
#define ROWS  (BATCH*POS)                  // 202500
#define TILE_M 64
#define TILES ((ROWS + TILE_M - 1) / TILE_M)   // 3165

// Allocation-free scratch
__device__ float         g_nk[256 * M_DIM];
__device__ __nv_bfloat16 g_Bh[M_DIM * M_DIM];   // B[n][k] = M[n][k], hi part
__device__ __nv_bfloat16 g_Bl[M_DIM * M_DIM];   // lo part

// ---------------------------------------------------------------------------
__global__ void nk_kernel(const float* __restrict__ Acoeff,
                          const float* __restrict__ Bbasis) {
    int e = blockIdx.x * blockDim.x + threadIdx.x;  // 0..32767
    int idx = e >> 7, j = e & 127;
    g_nk[e] = Acoeff[j * 256 + idx] * Bbasis[idx * M_DIM + j];
}

__global__ void prep_b_kernel(const float* __restrict__ Mmat) {
    int e = blockIdx.x * blockDim.x + threadIdx.x;  // 0..16383
    float v = Mmat[e];
    __nv_bfloat16 hi = __float2bfloat16_rn(v);
    __nv_bfloat16 lo = __float2bfloat16_rn(v - __bfloat162float(hi));
    g_Bh[e] = hi;
    g_Bl[e] = lo;
}

// ---------------------------------------------------------------------------
__device__ __forceinline__ uint32_t smem_u32(const void* p) {
    uint32_t a;
    asm("{ .reg .u64 t; cvta.to.shared.u64 t, %1; cvt.u32.u64 %0, t; }"
        : "=r"(a) : "l"(p));
    return a;
}
__device__ __forceinline__ uint32_t pack_bf16(__nv_bfloat16 a, __nv_bfloat16 b) {
    return ((uint32_t)__bfloat16_as_ushort(b) << 16) | __bfloat16_as_ushort(a);
}
__device__ __forceinline__ void split2(float x, float y, uint32_t& hi, uint32_t& lo) {
    __nv_bfloat16 hx = __float2bfloat16_rn(x);
    __nv_bfloat16 hy = __float2bfloat16_rn(y);
    __nv_bfloat16 lx = __float2bfloat16_rn(x - __bfloat162float(hx));
    __nv_bfloat16 ly = __float2bfloat16_rn(y - __bfloat162float(hy));
    hi = pack_bf16(hx, hy);
    lo = pack_bf16(lx, ly);
}
__device__ __forceinline__ void mma_bf16(float* c, const uint32_t* a, const uint32_t* b) {
    asm volatile(
        "mma.sync.aligned.m16n8k16.row.col.f32.bf16.bf16.f32 "
        "{%0,%1,%2,%3}, {%4,%5,%6,%7}, {%8,%9}, {%0,%1,%2,%3};"
        : "+f"(c[0]), "+f"(c[1]), "+f"(c[2]), "+f"(c[3])
        : "r"(a[0]), "r"(a[1]), "r"(a[2]), "r"(a[3]), "r"(b[0]), "r"(b[1]));
}
__device__ __forceinline__ void ldm_x4(uint32_t (&r)[4], uint32_t addr) {
    asm volatile("ldmatrix.sync.aligned.m8n8.x4.shared.b16 {%0,%1,%2,%3}, [%4];"
        : "=r"(r[0]), "=r"(r[1]), "=r"(r[2]), "=r"(r[3]) : "r"(addr));
}

// ---------------------------------------------------------------------------
// SMEM: pitch 272B => rows r hit word banks 4r mod 32: ldmatrix 8-row phases
// conflict-free (also at +16B and +16 rows, 272*16 % 128 == 0).
// ---------------------------------------------------------------------------
#define PITCH_B   272
#define OFF_A_HI  0
#define OFF_A_LO  (TILE_M * PITCH_B)           // 17408
#define OFF_B_HI  (2 * TILE_M * PITCH_B)       // 34816
#define OFF_B_LO  (OFF_B_HI + 128 * PITCH_B)   // 69632
#define SMEM_TOTAL (OFF_B_LO + 128 * PITCH_B)  // 104448

__global__ void __launch_bounds__(256, 2)
fused_kernel(const float4* __restrict__ vec, float* __restrict__ out) {
    extern __shared__ char smem[];
    const uint32_t sb = smem_u32(smem);
    const int t    = threadIdx.x;
    const int wid  = t >> 5;
    const int lane = t & 31;
    const int row0 = blockIdx.x * TILE_M;

    // ---- B tiles: copy preconverted bf16 hi/lo ----
    {
        const uint4* bh = (const uint4*)g_Bh;
        const uint4* bl = (const uint4*)g_Bl;
#pragma unroll
        for (int e = t; e < 2048; e += 256) {          // 128 rows x 16 uint4
            int n = e >> 4, c = e & 15;
            uint32_t off = (uint32_t)(n * PITCH_B + c * 16);
            *(uint4*)(smem + OFF_B_HI + off) = __ldg(&bh[e]);
            *(uint4*)(smem + OFF_B_LO + off) = __ldg(&bl[e]);
        }
    }

    // ---- A gather: run-streaming pool. task = (8-row chunk, q) ----
    {
        const int S4 = 32, S3 = 512, S2 = 8192, S1 = 131072;  // float4 strides
        const long long SBATCH = (long long)S1 * D_DIM;
        const int sub = t >> 5;          // 8-row chunk
        const int q   = lane;            // float4 channel chunk
        int r    = row0 + sub * 8;
        int gend = r + 8;
        if (gend > ROWS) gend = ROWS;

        while (r < gend) {
            int b   = r / POS;
            int pos = r - b * POS;
            int k4  = pos % W_DIM;
            int r1  = pos / W_DIM;
            int k3  = r1 % W_DIM;
            int r2  = r1 / W_DIM;
            int k2  = r2 % W_DIM;
            int k1  = r2 / W_DIM;
            int segend = r + (W_DIM - k4);
            if (segend > gend) segend = gend;
            const int L = segend - r;

            const float4* p = vec + b * SBATCH + k1 * S1 + k2 * S2
                                  + k3 * S3 + k4 * S4 + q;
            const int co1 = S3, co2 = S2, co3 = S2 + S3;
            const int co4 = S1, co5 = S1 + S3, co6 = S1 + S2, co7 = S1 + S2 + S3;

            float4 sp;
            {
                float sx = 0.f, sy = 0.f, sz = 0.f, sw = 0.f;
                float4 v;
                v = __ldg(p);        sx += v.x; sy += v.y; sz += v.z; sw += v.w;
                v = __ldg(p + co1);  sx += v.x; sy += v.y; sz += v.z; sw += v.w;
                v = __ldg(p + co2);  sx += v.x; sy += v.y; sz += v.z; sw += v.w;
                v = __ldg(p + co3);  sx += v.x; sy += v.y; sz += v.z; sw += v.w;
                v = __ldg(p + co4);  sx += v.x; sy += v.y; sz += v.z; sw += v.w;
                v = __ldg(p + co5);  sx += v.x; sy += v.y; sz += v.z; sw += v.w;
                v = __ldg(p + co6);  sx += v.x; sy += v.y; sz += v.z; sw += v.w;
                v = __ldg(p + co7);  sx += v.x; sy += v.y; sz += v.z; sw += v.w;
                sp = make_float4(sx, sy, sz, sw);
            }
            for (int j = 1; j <= L; j++) {
                const float4* pj = p + j * S4;
                float sx = 0.f, sy = 0.f, sz = 0.f, sw = 0.f;
                float4 v;
                v = __ldg(pj);       sx += v.x; sy += v.y; sz += v.z; sw += v.w;
                v = __ldg(pj + co1); sx += v.x; sy += v.y; sz += v.z; sw += v.w;
                v = __ldg(pj + co2); sx += v.x; sy += v.y; sz += v.z; sw += v.w;
                v = __ldg(pj + co3); sx += v.x; sy += v.y; sz += v.z; sw += v.w;
                v = __ldg(pj + co4); sx += v.x; sy += v.y; sz += v.z; sw += v.w;
                v = __ldg(pj + co5); sx += v.x; sy += v.y; sz += v.z; sw += v.w;
                v = __ldg(pj + co6); sx += v.x; sy += v.y; sz += v.z; sw += v.w;
                v = __ldg(pj + co7); sx += v.x; sy += v.y; sz += v.z; sw += v.w;

                float ox = (sp.x + sx) * 0.0625f;
                float oy = (sp.y + sy) * 0.0625f;
                float oz = (sp.z + sz) * 0.0625f;
                float ow = (sp.w + sw) * 0.0625f;
                sp = make_float4(sx, sy, sz, sw);

                uint2 hv, lv;
                split2(ox, oy, hv.x, lv.x);
                split2(oz, ow, hv.y, lv.y);
                int rl = r + j - 1 - row0;
                uint32_t off = (uint32_t)(rl * PITCH_B + q * 8);
                *(uint2*)(smem + OFF_A_HI + off) = hv;
                *(uint2*)(smem + OFF_A_LO + off) = lv;
            }
            r = segend;
        }
    }
    __syncthreads();

    // ---- Mainloop: warp tile 32(m) x 32(n); ldmatrix + 3 split MMA passes ----
    const int wm = wid & 1;
    const int wn = wid >> 1;

    // A: lanes 0-15 -> m rows (lane&15), khalf 0; lanes 16-31 -> same rows, +16B
    const uint32_t aHi = sb + OFF_A_HI
        + (uint32_t)((wm * 32 + (lane & 15)) * PITCH_B + (lane >> 4) * 16);
    const uint32_t aLo = aHi + (OFF_A_LO - OFF_A_HI);
    // B: lanes 0-7 n+0 kh0 | 8-15 n+0 kh1 | 16-23 n+8 kh0 | 24-31 n+8 kh1
    const uint32_t bHi = sb + OFF_B_HI
        + (uint32_t)((wn * 32 + (lane & 7) + (lane >> 4) * 8) * PITCH_B
                     + ((lane >> 3) & 1) * 16);
    const uint32_t bLo = bHi + (OFF_B_LO - OFF_B_HI);

    float acc[2][4][4];
#pragma unroll
    for (int mt = 0; mt < 2; mt++)
#pragma unroll
        for (int nt = 0; nt < 4; nt++)
#pragma unroll
            for (int i = 0; i < 4; i++) acc[mt][nt][i] = 0.f;

#pragma unroll
    for (int ks = 0; ks < 8; ks++) {
        const uint32_t koff = ks * 32;
        uint32_t ah[2][4], al[2][4], bhf[2][4], blf[2][4];
        ldm_x4(ah[0], aHi + koff);
        ldm_x4(ah[1], aHi + 16 * PITCH_B + koff);
        ldm_x4(al[0], aLo + koff);
        ldm_x4(al[1], aLo + 16 * PITCH_B + koff);
        ldm_x4(bhf[0], bHi + koff);
        ldm_x4(bhf[1], bHi + 16 * PITCH_B + koff);
        ldm_x4(blf[0], bLo + koff);
        ldm_x4(blf[1], bLo + 16 * PITCH_B + koff);
#pragma unroll
        for (int mt = 0; mt < 2; mt++)
#pragma unroll
            for (int nt = 0; nt < 4; nt++) {
                const uint32_t* b2h = &bhf[nt >> 1][(nt & 1) * 2];
                const uint32_t* b2l = &blf[nt >> 1][(nt & 1) * 2];
                mma_bf16(acc[mt][nt], ah[mt], b2h);   // hi*hi
                mma_bf16(acc[mt][nt], al[mt], b2h);   // lo*hi
                mma_bf16(acc[mt][nt], ah[mt], b2l);   // hi*lo
            }
    }

    // ---- Epilogue: out[row][col] = Nk[idx(row)][col] - acc ----
    const int g  = lane >> 2;
    const int cq = (lane & 3) * 2;
#pragma unroll
    for (int mt = 0; mt < 2; mt++) {
#pragma unroll
        for (int half = 0; half < 2; half++) {
            int row = row0 + wm * 32 + mt * 16 + g + half * 8;
            if (row >= ROWS) continue;
            int pos = row % POS;
            int k4 = pos % W_DIM;
            int q1 = pos / W_DIM;
            int k3 = q1 % W_DIM;
            int q2 = q1 / W_DIM;
            int k2 = q2 % W_DIM;
            int k1 = q2 / W_DIM;
            int idx = (((k1 & 3) * 4 + (k2 & 3)) * 4 + (k3 & 3)) * 4 + (k4 & 3);
            const float* nkrow = g_nk + idx * M_DIM;
            float* orow = out + (long long)row * M_DIM;
#pragma unroll
            for (int nt = 0; nt < 4; nt++) {
                int c0 = wn * 32 + nt * 8 + cq;
                float2 nk = __ldg((const float2*)(nkrow + c0));
                float2 o;
                o.x = nk.x - acc[mt][nt][half * 2 + 0];
                o.y = nk.y - acc[mt][nt][half * 2 + 1];
                *(float2*)(orow + c0) = o;
            }
        }
    }
}

// ---------------------------------------------------------------------------
extern "C" void kernel_launch(void* const* d_in, const int* in_sizes, int n_in,
                              void* d_out, int out_size) {
    const float* vec    = (const float*)d_in[0];   // (4,16,16,16,16,128)
    const float* Mmat   = (const float*)d_in[1];   // (128,128)
    const float* Acoeff = (const float*)d_in[2];   // (128,256)
    const float* Bbasis = (const float*)d_in[3];   // (256,128)
    float* out = (float*)d_out;                    // (4, 50625, 128)

    cudaFuncSetAttribute(fused_kernel,
                         cudaFuncAttributeMaxDynamicSharedMemorySize,
                         SMEM_TOTAL);

    nk_kernel<<<128, 256>>>(Acoeff, Bbasis);
    prep_b_kernel<<<64, 256>>>(Mmat);
    fused_kernel<<<TILES, 256, SMEM_TOTAL>>>((const float4*)vec, out);
}

// round 6
// speedup vs baseline: 1.6538x; 1.0916x over previous
#include <cuda_runtime.h>
#include <cuda_bf16.h>
#include <cstdint>

#define M_DIM 128
#define D_DIM 16
#define W_DIM 15
#define POS   (W_DIM*W_DIM*W_DIM*W_DIM)   // 50625
#define BATCH 4
#define ROWS  (BATCH*POS)                  // 202500
#define TILE_M 64
#define TILES ((ROWS + TILE_M - 1) / TILE_M)   // 3165
#define PADROWS (TILES * TILE_M)               // 202560

// Allocation-free scratch (__device__ globals)
__device__ float         g_nk[256 * M_DIM];
__device__ __nv_bfloat16 g_Bh[M_DIM * M_DIM];
__device__ __nv_bfloat16 g_Bl[M_DIM * M_DIM];
__device__ __nv_bfloat16 g_Ah[(size_t)PADROWS * M_DIM];   // ~52 MB
__device__ __nv_bfloat16 g_Al[(size_t)PADROWS * M_DIM];   // ~52 MB

// ---------------------------------------------------------------------------
// helpers
// ---------------------------------------------------------------------------
__device__ __forceinline__ uint32_t smem_u32(const void* p) {
    uint32_t a;
    asm("{ .reg .u64 t; cvta.to.shared.u64 t, %1; cvt.u32.u64 %0, t; }"
        : "=r"(a) : "l"(p));
    return a;
}
__device__ __forceinline__ uint32_t pack_bf16(__nv_bfloat16 a, __nv_bfloat16 b) {
    return ((uint32_t)__bfloat16_as_ushort(b) << 16) | __bfloat16_as_ushort(a);
}
__device__ __forceinline__ void split2(float x, float y, uint32_t& hi, uint32_t& lo) {
    __nv_bfloat16 hx = __float2bfloat16_rn(x);
    __nv_bfloat16 hy = __float2bfloat16_rn(y);
    __nv_bfloat16 lx = __float2bfloat16_rn(x - __bfloat162float(hx));
    __nv_bfloat16 ly = __float2bfloat16_rn(y - __bfloat162float(hy));
    hi = pack_bf16(hx, hy);
    lo = pack_bf16(lx, ly);
}
__device__ __forceinline__ void mma_bf16(float* c, const uint32_t* a, const uint32_t* b) {
    asm volatile(
        "mma.sync.aligned.m16n8k16.row.col.f32.bf16.bf16.f32 "
        "{%0,%1,%2,%3}, {%4,%5,%6,%7}, {%8,%9}, {%0,%1,%2,%3};"
        : "+f"(c[0]), "+f"(c[1]), "+f"(c[2]), "+f"(c[3])
        : "r"(a[0]), "r"(a[1]), "r"(a[2]), "r"(a[3]), "r"(b[0]), "r"(b[1]));
}
__device__ __forceinline__ void ldm_x4(uint32_t (&r)[4], uint32_t addr) {
    asm volatile("ldmatrix.sync.aligned.m8n8.x4.shared.b16 {%0,%1,%2,%3}, [%4];"
        : "=r"(r[0]), "=r"(r[1]), "=r"(r[2]), "=r"(r[3]) : "r"(addr));
}
#define CP_ASYNC_CG(dst, src) \
    asm volatile("cp.async.cg.shared.global [%0], [%1], 16;" \
                 :: "r"(dst), "l"(src) : "memory")
#define CP_ASYNC_COMMIT() asm volatile("cp.async.commit_group;" ::: "memory")
#define CP_ASYNC_WAIT0()  asm volatile("cp.async.wait_group 0;" ::: "memory")

// ---------------------------------------------------------------------------
// Prep (one launch): e<32768 -> Nk table; else -> B hi/lo split
// ---------------------------------------------------------------------------
__global__ void prep_kernel(const float* __restrict__ Acoeff,
                            const float* __restrict__ Bbasis,
                            const float* __restrict__ Mmat) {
    int e = blockIdx.x * blockDim.x + threadIdx.x;   // 0..49151
    if (e < 32768) {
        int idx = e >> 7, j = e & 127;
        g_nk[e] = Acoeff[j * 256 + idx] * Bbasis[idx * M_DIM + j];
    } else {
        int e2 = e - 32768;                           // 0..16383
        float v = Mmat[e2];
        __nv_bfloat16 hi = __float2bfloat16_rn(v);
        __nv_bfloat16 lo = __float2bfloat16_rn(v - __bfloat162float(hi));
        g_Bh[e2] = hi;
        g_Bl[e2] = lo;
    }
}

// ---------------------------------------------------------------------------
// Pool: run-streaming 2^4 mean-pool -> bf16 hi/lo, straight to gmem.
// warp = 8-row chunk, lane = 16B channel chunk. High occupancy, no smem.
// ---------------------------------------------------------------------------
__global__ void __launch_bounds__(256)
pool_kernel(const float4* __restrict__ vec) {
    const int t    = threadIdx.x;
    const int lane = t & 31;
    const int sub  = t >> 5;
    const int q    = lane;
    int r    = blockIdx.x * 64 + sub * 8;
    int rend = r + 8;

    // zero any padded rows
    for (int rr = (r < ROWS ? ROWS : r); rr < rend; rr++) {
        uint2 z = make_uint2(0u, 0u);
        ((uint2*)g_Ah)[(size_t)rr * 32 + q] = z;
        ((uint2*)g_Al)[(size_t)rr * 32 + q] = z;
    }
    int gend = rend < ROWS ? rend : ROWS;

    const int S4 = 32, S3 = 512, S2 = 8192, S1 = 131072;  // float4 strides
    const long long SBATCH = (long long)S1 * D_DIM;

    while (r < gend) {
        int b   = r / POS;
        int pos = r - b * POS;
        int k4  = pos % W_DIM;
        int r1  = pos / W_DIM;
        int k3  = r1 % W_DIM;
        int r2  = r1 / W_DIM;
        int k2  = r2 % W_DIM;
        int k1  = r2 / W_DIM;
        int segend = r + (W_DIM - k4);
        if (segend > gend) segend = gend;
        const int L = segend - r;

        const float4* p = vec + b * SBATCH + k1 * S1 + k2 * S2
                              + k3 * S3 + k4 * S4 + q;
        const int co1 = S3, co2 = S2, co3 = S2 + S3;
        const int co4 = S1, co5 = S1 + S3, co6 = S1 + S2, co7 = S1 + S2 + S3;

        float4 sp;
        {
            float sx = 0.f, sy = 0.f, sz = 0.f, sw = 0.f;
            float4 v;
            v = __ldg(p);        sx += v.x; sy += v.y; sz += v.z; sw += v.w;
            v = __ldg(p + co1);  sx += v.x; sy += v.y; sz += v.z; sw += v.w;
            v = __ldg(p + co2);  sx += v.x; sy += v.y; sz += v.z; sw += v.w;
            v = __ldg(p + co3);  sx += v.x; sy += v.y; sz += v.z; sw += v.w;
            v = __ldg(p + co4);  sx += v.x; sy += v.y; sz += v.z; sw += v.w;
            v = __ldg(p + co5);  sx += v.x; sy += v.y; sz += v.z; sw += v.w;
            v = __ldg(p + co6);  sx += v.x; sy += v.y; sz += v.z; sw += v.w;
            v = __ldg(p + co7);  sx += v.x; sy += v.y; sz += v.z; sw += v.w;
            sp = make_float4(sx, sy, sz, sw);
        }
        for (int j = 1; j <= L; j++) {
            const float4* pj = p + j * S4;
            float sx = 0.f, sy = 0.f, sz = 0.f, sw = 0.f;
            float4 v;
            v = __ldg(pj);       sx += v.x; sy += v.y; sz += v.z; sw += v.w;
            v = __ldg(pj + co1); sx += v.x; sy += v.y; sz += v.z; sw += v.w;
            v = __ldg(pj + co2); sx += v.x; sy += v.y; sz += v.z; sw += v.w;
            v = __ldg(pj + co3); sx += v.x; sy += v.y; sz += v.z; sw += v.w;
            v = __ldg(pj + co4); sx += v.x; sy += v.y; sz += v.z; sw += v.w;
            v = __ldg(pj + co5); sx += v.x; sy += v.y; sz += v.z; sw += v.w;
            v = __ldg(pj + co6); sx += v.x; sy += v.y; sz += v.z; sw += v.w;
            v = __ldg(pj + co7); sx += v.x; sy += v.y; sz += v.z; sw += v.w;

            float ox = (sp.x + sx) * 0.0625f;
            float oy = (sp.y + sy) * 0.0625f;
            float oz = (sp.z + sz) * 0.0625f;
            float ow = (sp.w + sw) * 0.0625f;
            sp = make_float4(sx, sy, sz, sw);

            uint2 hv, lv;
            split2(ox, oy, hv.x, lv.x);
            split2(oz, ow, hv.y, lv.y);
            size_t orow = (size_t)(r + j - 1) * 32 + q;
            ((uint2*)g_Ah)[orow] = hv;
            ((uint2*)g_Al)[orow] = lv;
        }
        r = segend;
    }
}

// ---------------------------------------------------------------------------
// GEMM: cp.async tile load -> ldmatrix + 3-pass split-bf16 MMA -> Nk epilogue
// SMEM pitch 272B: ldmatrix 8-row phases conflict-free.
// ---------------------------------------------------------------------------
#define PITCH_B   272
#define OFF_A_HI  0
#define OFF_A_LO  (TILE_M * PITCH_B)           // 17408
#define OFF_B_HI  (2 * TILE_M * PITCH_B)       // 34816
#define OFF_B_LO  (OFF_B_HI + 128 * PITCH_B)   // 69632
#define SMEM_TOTAL (OFF_B_LO + 128 * PITCH_B)  // 104448

__global__ void __launch_bounds__(256, 2)
gemm_kernel(float* __restrict__ out) {
    extern __shared__ char smem[];
    const uint32_t sb = smem_u32(smem);
    const int t    = threadIdx.x;
    const int wid  = t >> 5;
    const int lane = t & 31;
    const int row0 = blockIdx.x * TILE_M;

    // ---- cp.async loads: A (64 rows) + B (128 rows), hi+lo ----
    {
        const char* ah = (const char*)g_Ah + (size_t)row0 * 256;
        const char* al = (const char*)g_Al + (size_t)row0 * 256;
#pragma unroll
        for (int i = 0; i < 4; i++) {                 // 1024 chunks / 256 thr
            int e = t + i * 256;
            int r = e >> 4, c = e & 15;
            uint32_t off = (uint32_t)(r * PITCH_B + c * 16);
            CP_ASYNC_CG(sb + OFF_A_HI + off, ah + r * 256 + c * 16);
            CP_ASYNC_CG(sb + OFF_A_LO + off, al + r * 256 + c * 16);
        }
        const char* bh = (const char*)g_Bh;
        const char* bl = (const char*)g_Bl;
#pragma unroll
        for (int i = 0; i < 8; i++) {                 // 2048 chunks / 256 thr
            int e = t + i * 256;
            int r = e >> 4, c = e & 15;
            uint32_t off = (uint32_t)(r * PITCH_B + c * 16);
            CP_ASYNC_CG(sb + OFF_B_HI + off, bh + r * 256 + c * 16);
            CP_ASYNC_CG(sb + OFF_B_LO + off, bl + r * 256 + c * 16);
        }
        CP_ASYNC_COMMIT();
        CP_ASYNC_WAIT0();
    }
    __syncthreads();

    // ---- Mainloop: warp tile 32(m) x 32(n) ----
    const int wm = wid & 1;
    const int wn = wid >> 1;

    const uint32_t aHi = sb + OFF_A_HI
        + (uint32_t)((wm * 32 + (lane & 15)) * PITCH_B + (lane >> 4) * 16);
    const uint32_t aLo = aHi + (OFF_A_LO - OFF_A_HI);
    const uint32_t bHi = sb + OFF_B_HI
        + (uint32_t)((wn * 32 + (lane & 7) + (lane >> 4) * 8) * PITCH_B
                     + ((lane >> 3) & 1) * 16);
    const uint32_t bLo = bHi + (OFF_B_LO - OFF_B_HI);

    float acc[2][4][4];
#pragma unroll
    for (int mt = 0; mt < 2; mt++)
#pragma unroll
        for (int nt = 0; nt < 4; nt++)
#pragma unroll
            for (int i = 0; i < 4; i++) acc[mt][nt][i] = 0.f;

#pragma unroll
    for (int ks = 0; ks < 8; ks++) {
        const uint32_t koff = ks * 32;
        uint32_t ah[2][4], al[2][4], bhf[2][4], blf[2][4];
        ldm_x4(ah[0], aHi + koff);
        ldm_x4(ah[1], aHi + 16 * PITCH_B + koff);
        ldm_x4(al[0], aLo + koff);
        ldm_x4(al[1], aLo + 16 * PITCH_B + koff);
        ldm_x4(bhf[0], bHi + koff);
        ldm_x4(bhf[1], bHi + 16 * PITCH_B + koff);
        ldm_x4(blf[0], bLo + koff);
        ldm_x4(blf[1], bLo + 16 * PITCH_B + koff);
#pragma unroll
        for (int mt = 0; mt < 2; mt++)
#pragma unroll
            for (int nt = 0; nt < 4; nt++) {
                const uint32_t* b2h = &bhf[nt >> 1][(nt & 1) * 2];
                const uint32_t* b2l = &blf[nt >> 1][(nt & 1) * 2];
                mma_bf16(acc[mt][nt], ah[mt], b2h);   // hi*hi
                mma_bf16(acc[mt][nt], al[mt], b2h);   // lo*hi
                mma_bf16(acc[mt][nt], ah[mt], b2l);   // hi*lo
            }
    }

    // ---- Epilogue: out[row][col] = Nk[idx(row)][col] - acc ----
    const int g  = lane >> 2;
    const int cq = (lane & 3) * 2;
#pragma unroll
    for (int mt = 0; mt < 2; mt++) {
#pragma unroll
        for (int half = 0; half < 2; half++) {
            int row = row0 + wm * 32 + mt * 16 + g + half * 8;
            if (row >= ROWS) continue;
            int pos = row % POS;
            int k4 = pos % W_DIM;
            int q1 = pos / W_DIM;
            int k3 = q1 % W_DIM;
            int q2 = q1 / W_DIM;
            int k2 = q2 % W_DIM;
            int k1 = q2 / W_DIM;
            int idx = (((k1 & 3) * 4 + (k2 & 3)) * 4 + (k3 & 3)) * 4 + (k4 & 3);
            const float* nkrow = g_nk + idx * M_DIM;
            float* orow = out + (long long)row * M_DIM;
#pragma unroll
            for (int nt = 0; nt < 4; nt++) {
                int c0 = wn * 32 + nt * 8 + cq;
                float2 nk = __ldg((const float2*)(nkrow + c0));
                float2 o;
                o.x = nk.x - acc[mt][nt][half * 2 + 0];
                o.y = nk.y - acc[mt][nt][half * 2 + 1];
                *(float2*)(orow + c0) = o;
            }
        }
    }
}

// ---------------------------------------------------------------------------
extern "C" void kernel_launch(void* const* d_in, const int* in_sizes, int n_in,
                              void* d_out, int out_size) {
    const float* vec    = (const float*)d_in[0];   // (4,16,16,16,16,128)
    const float* Mmat   = (const float*)d_in[1];   // (128,128)
    const float* Acoeff = (const float*)d_in[2];   // (128,256)
    const float* Bbasis = (const float*)d_in[3];   // (256,128)
    float* out = (float*)d_out;                    // (4, 50625, 128)

    cudaFuncSetAttribute(gemm_kernel,
                         cudaFuncAttributeMaxDynamicSharedMemorySize,
                         SMEM_TOTAL);

    prep_kernel<<<192, 256>>>(Acoeff, Bbasis, Mmat);
    pool_kernel<<<TILES, 256>>>((const float4*)vec);
    gemm_kernel<<<TILES, 256, SMEM_TOTAL>>>(out);
}

// round 7
// speedup vs baseline: 1.7525x; 1.0597x over previous
#include <cuda_runtime.h>
#include <cuda_bf16.h>
#include <cstdint>

#define M_DIM 128
#define D_DIM 16
#define W_DIM 15
#define POS   (W_DIM*W_DIM*W_DIM*W_DIM)   // 50625
#define BATCH 4
#define ROWS  (BATCH*POS)                  // 202500
#define TILE_M 64
#define TILES ((ROWS + TILE_M - 1) / TILE_M)   // 3165
#define PADROWS (TILES * TILE_M)               // 202560
#define GRID_GEMM 296                          // 2 CTAs/SM persistent

// Allocation-free scratch (__device__ globals)
__device__ float         g_nk[256 * M_DIM];
__device__ __nv_bfloat16 g_Bh[M_DIM * M_DIM];
__device__ __nv_bfloat16 g_Bl[M_DIM * M_DIM];
__device__ __nv_bfloat16 g_Ah[(size_t)PADROWS * M_DIM];   // ~52 MB
__device__ __nv_bfloat16 g_Al[(size_t)PADROWS * M_DIM];   // ~52 MB

// ---------------------------------------------------------------------------
// helpers
// ---------------------------------------------------------------------------
__device__ __forceinline__ uint32_t smem_u32(const void* p) {
    uint32_t a;
    asm("{ .reg .u64 t; cvta.to.shared.u64 t, %1; cvt.u32.u64 %0, t; }"
        : "=r"(a) : "l"(p));
    return a;
}
__device__ __forceinline__ uint32_t pack_bf16(__nv_bfloat16 a, __nv_bfloat16 b) {
    return ((uint32_t)__bfloat16_as_ushort(b) << 16) | __bfloat16_as_ushort(a);
}
__device__ __forceinline__ void split2(float x, float y, uint32_t& hi, uint32_t& lo) {
    __nv_bfloat16 hx = __float2bfloat16_rn(x);
    __nv_bfloat16 hy = __float2bfloat16_rn(y);
    __nv_bfloat16 lx = __float2bfloat16_rn(x - __bfloat162float(hx));
    __nv_bfloat16 ly = __float2bfloat16_rn(y - __bfloat162float(hy));
    hi = pack_bf16(hx, hy);
    lo = pack_bf16(lx, ly);
}
__device__ __forceinline__ void mma_bf16(float* c, const uint32_t* a, const uint32_t* b) {
    asm volatile(
        "mma.sync.aligned.m16n8k16.row.col.f32.bf16.bf16.f32 "
        "{%0,%1,%2,%3}, {%4,%5,%6,%7}, {%8,%9}, {%0,%1,%2,%3};"
        : "+f"(c[0]), "+f"(c[1]), "+f"(c[2]), "+f"(c[3])
        : "r"(a[0]), "r"(a[1]), "r"(a[2]), "r"(a[3]), "r"(b[0]), "r"(b[1]));
}
__device__ __forceinline__ void ldm_x4(uint32_t (&r)[4], uint32_t addr) {
    asm volatile("ldmatrix.sync.aligned.m8n8.x4.shared.b16 {%0,%1,%2,%3}, [%4];"
        : "=r"(r[0]), "=r"(r[1]), "=r"(r[2]), "=r"(r[3]) : "r"(addr));
}
#define CP_ASYNC_CG(dst, src) \
    asm volatile("cp.async.cg.shared.global [%0], [%1], 16;" \
                 :: "r"(dst), "l"(src) : "memory")
#define CP_ASYNC_COMMIT() asm volatile("cp.async.commit_group;" ::: "memory")
#define CP_ASYNC_WAIT1()  asm volatile("cp.async.wait_group 1;" ::: "memory")

// ---------------------------------------------------------------------------
// Pool (+ folded prep): run-streaming 2^4 mean-pool -> bf16 hi/lo to gmem.
// Blocks 0..191 additionally build the Nk table and the B hi/lo split.
// ---------------------------------------------------------------------------
__global__ void __launch_bounds__(256)
pool_kernel(const float4* __restrict__ vec,
            const float* __restrict__ Acoeff,
            const float* __restrict__ Bbasis,
            const float* __restrict__ Mmat) {
    const int t = threadIdx.x;

    // folded prep: 192*256 = 49152 elements
    if (blockIdx.x < 192) {
        int e = blockIdx.x * 256 + t;
        if (e < 32768) {
            int idx = e >> 7, j = e & 127;
            g_nk[e] = Acoeff[j * 256 + idx] * Bbasis[idx * M_DIM + j];
        } else {
            int e2 = e - 32768;                  // 0..16383
            float v = Mmat[e2];
            __nv_bfloat16 hi = __float2bfloat16_rn(v);
            __nv_bfloat16 lo = __float2bfloat16_rn(v - __bfloat162float(hi));
            g_Bh[e2] = hi;
            g_Bl[e2] = lo;
        }
    }

    const int lane = t & 31;
    const int sub  = t >> 5;
    const int q    = lane;
    int r    = blockIdx.x * 64 + sub * 8;
    int rend = r + 8;

    for (int rr = (r < ROWS ? ROWS : r); rr < rend; rr++) {
        uint2 z = make_uint2(0u, 0u);
        ((uint2*)g_Ah)[(size_t)rr * 32 + q] = z;
        ((uint2*)g_Al)[(size_t)rr * 32 + q] = z;
    }
    int gend = rend < ROWS ? rend : ROWS;

    const int S4 = 32, S3 = 512, S2 = 8192, S1 = 131072;  // float4 strides
    const long long SBATCH = (long long)S1 * D_DIM;

    while (r < gend) {
        int b   = r / POS;
        int pos = r - b * POS;
        int k4  = pos % W_DIM;
        int r1  = pos / W_DIM;
        int k3  = r1 % W_DIM;
        int r2  = r1 / W_DIM;
        int k2  = r2 % W_DIM;
        int k1  = r2 / W_DIM;
        int segend = r + (W_DIM - k4);
        if (segend > gend) segend = gend;
        const int L = segend - r;

        const float4* p = vec + b * SBATCH + k1 * S1 + k2 * S2
                              + k3 * S3 + k4 * S4 + q;
        const int co1 = S3, co2 = S2, co3 = S2 + S3;
        const int co4 = S1, co5 = S1 + S3, co6 = S1 + S2, co7 = S1 + S2 + S3;

        float4 sp;
        {
            float sx = 0.f, sy = 0.f, sz = 0.f, sw = 0.f;
            float4 v;
            v = __ldg(p);        sx += v.x; sy += v.y; sz += v.z; sw += v.w;
            v = __ldg(p + co1);  sx += v.x; sy += v.y; sz += v.z; sw += v.w;
            v = __ldg(p + co2);  sx += v.x; sy += v.y; sz += v.z; sw += v.w;
            v = __ldg(p + co3);  sx += v.x; sy += v.y; sz += v.z; sw += v.w;
            v = __ldg(p + co4);  sx += v.x; sy += v.y; sz += v.z; sw += v.w;
            v = __ldg(p + co5);  sx += v.x; sy += v.y; sz += v.z; sw += v.w;
            v = __ldg(p + co6);  sx += v.x; sy += v.y; sz += v.z; sw += v.w;
            v = __ldg(p + co7);  sx += v.x; sy += v.y; sz += v.z; sw += v.w;
            sp = make_float4(sx, sy, sz, sw);
        }
        for (int j = 1; j <= L; j++) {
            const float4* pj = p + j * S4;
            float sx = 0.f, sy = 0.f, sz = 0.f, sw = 0.f;
            float4 v;
            v = __ldg(pj);       sx += v.x; sy += v.y; sz += v.z; sw += v.w;
            v = __ldg(pj + co1); sx += v.x; sy += v.y; sz += v.z; sw += v.w;
            v = __ldg(pj + co2); sx += v.x; sy += v.y; sz += v.z; sw += v.w;
            v = __ldg(pj + co3); sx += v.x; sy += v.y; sz += v.z; sw += v.w;
            v = __ldg(pj + co4); sx += v.x; sy += v.y; sz += v.z; sw += v.w;
            v = __ldg(pj + co5); sx += v.x; sy += v.y; sz += v.z; sw += v.w;
            v = __ldg(pj + co6); sx += v.x; sy += v.y; sz += v.z; sw += v.w;
            v = __ldg(pj + co7); sx += v.x; sy += v.y; sz += v.z; sw += v.w;

            float ox = (sp.x + sx) * 0.0625f;
            float oy = (sp.y + sy) * 0.0625f;
            float oz = (sp.z + sz) * 0.0625f;
            float ow = (sp.w + sw) * 0.0625f;
            sp = make_float4(sx, sy, sz, sw);

            uint2 hv, lv;
            split2(ox, oy, hv.x, lv.x);
            split2(oz, ow, hv.y, lv.y);
            size_t orow = (size_t)(r + j - 1) * 32 + q;
            ((uint2*)g_Ah)[orow] = hv;
            ((uint2*)g_Al)[orow] = lv;
        }
        r = segend;
    }
}

// ---------------------------------------------------------------------------
// Persistent GEMM: B loaded once/CTA; A K-halves double-pumped via cp.async
// groups overlapping MMA + epilogue. ldmatrix + 3-pass split-bf16 MMA.
// B pitch 272B, A-half pitch 144B: both conflict-free for ldmatrix phases.
// ---------------------------------------------------------------------------
#define PITCH_B   272
#define PITCH_A   144
#define OFF_B_HI  0
#define OFF_B_LO  (128 * PITCH_B)              // 34816
#define OFF_A0_HI (2 * 128 * PITCH_B)          // 69632
#define OFF_A0_LO (OFF_A0_HI + 64 * PITCH_A)   // 78848
#define OFF_A1_HI (OFF_A0_HI + 2 * 64 * PITCH_A) // 88064
#define OFF_A1_LO (OFF_A0_HI + 3 * 64 * PITCH_A) // 97280
#define SMEM_TOTAL (OFF_A0_HI + 4 * 64 * PITCH_A) // 106496

// Load K-half h (cols h*128B..) of tile's A hi+lo: 1024 x 16B chunks
__device__ __forceinline__ void load_a_half(uint32_t sb, int tile, int h, int t) {
    const char* ah = (const char*)g_Ah;
    const char* al = (const char*)g_Al;
    const size_t rowbase = (size_t)tile * TILE_M;
    const uint32_t dhi = (h ? OFF_A1_HI : OFF_A0_HI);
    const uint32_t dlo = (h ? OFF_A1_LO : OFF_A0_LO);
#pragma unroll
    for (int i = 0; i < 2; i++) {
        int e = t + i * 256;            // 0..511
        int r = e >> 3, c = e & 7;      // row 0..63, 16B chunk 0..7
        uint32_t dst = (uint32_t)(r * PITCH_A + c * 16);
        size_t src = (rowbase + r) * 256 + h * 128 + c * 16;
        CP_ASYNC_CG(sb + dhi + dst, ah + src);
        CP_ASYNC_CG(sb + dlo + dst, al + src);
    }
}

__global__ void __launch_bounds__(256, 2)
gemm_kernel(float* __restrict__ out) {
    extern __shared__ char smem[];
    const uint32_t sb = smem_u32(smem);
    const int t    = threadIdx.x;
    const int wid  = t >> 5;
    const int lane = t & 31;

    const int wm = wid & 1;
    const int wn = wid >> 1;

    // ---- prologue: B (once) + A halves of first tile ----
    int tile = blockIdx.x;
    {
        const char* bh = (const char*)g_Bh;
        const char* bl = (const char*)g_Bl;
#pragma unroll
        for (int i = 0; i < 8; i++) {                 // 2048 chunks
            int e = t + i * 256;
            int r = e >> 4, c = e & 15;
            uint32_t off = (uint32_t)(r * PITCH_B + c * 16);
            CP_ASYNC_CG(sb + OFF_B_HI + off, bh + r * 256 + c * 16);
            CP_ASYNC_CG(sb + OFF_B_LO + off, bl + r * 256 + c * 16);
        }
        load_a_half(sb, tile, 0, t);
        CP_ASYNC_COMMIT();                            // G: B + A0(t0)
        load_a_half(sb, tile, 1, t);
        CP_ASYNC_COMMIT();                            // G: A1(t0)
    }

    // fragment base addresses
    const uint32_t a0Hi = sb + OFF_A0_HI
        + (uint32_t)((wm * 32 + (lane & 15)) * PITCH_A + (lane >> 4) * 16);
    const uint32_t a0Lo = a0Hi + (OFF_A0_LO - OFF_A0_HI);
    const uint32_t a1Hi = a0Hi + (OFF_A1_HI - OFF_A0_HI);
    const uint32_t a1Lo = a0Hi + (OFF_A1_LO - OFF_A0_HI);
    const uint32_t bHi = sb + OFF_B_HI
        + (uint32_t)((wn * 32 + (lane & 7) + (lane >> 4) * 8) * PITCH_B
                     + ((lane >> 3) & 1) * 16);
    const uint32_t bLo = bHi + (OFF_B_LO - OFF_B_HI);

    const int g  = lane >> 2;
    const int cq = (lane & 3) * 2;

    for (; tile < TILES; tile += GRID_GEMM) {
        const int next = tile + GRID_GEMM;
        float acc[2][4][4];
#pragma unroll
        for (int mt = 0; mt < 2; mt++)
#pragma unroll
            for (int nt = 0; nt < 4; nt++)
#pragma unroll
                for (int i = 0; i < 4; i++) acc[mt][nt][i] = 0.f;

        // ---- half 0 (K 0..63) ----
        CP_ASYNC_WAIT1();
        __syncthreads();
#pragma unroll
        for (int ks = 0; ks < 4; ks++) {
            const uint32_t koff = ks * 32;
            const uint32_t kb   = ks * 32;   // B uses absolute K offset
            uint32_t ah[2][4], al[2][4], bhf[2][4], blf[2][4];
            ldm_x4(ah[0], a0Hi + koff);
            ldm_x4(ah[1], a0Hi + 16 * PITCH_A + koff);
            ldm_x4(al[0], a0Lo + koff);
            ldm_x4(al[1], a0Lo + 16 * PITCH_A + koff);
            ldm_x4(bhf[0], bHi + kb);
            ldm_x4(bhf[1], bHi + 16 * PITCH_B + kb);
            ldm_x4(blf[0], bLo + kb);
            ldm_x4(blf[1], bLo + 16 * PITCH_B + kb);
#pragma unroll
            for (int mt = 0; mt < 2; mt++)
#pragma unroll
                for (int nt = 0; nt < 4; nt++) {
                    const uint32_t* b2h = &bhf[nt >> 1][(nt & 1) * 2];
                    const uint32_t* b2l = &blf[nt >> 1][(nt & 1) * 2];
                    mma_bf16(acc[mt][nt], ah[mt], b2h);
                    mma_bf16(acc[mt][nt], al[mt], b2h);
                    mma_bf16(acc[mt][nt], ah[mt], b2l);
                }
        }
        __syncthreads();                       // all warps done reading A0
        if (next < TILES) load_a_half(sb, next, 0, t);
        CP_ASYNC_COMMIT();

        // ---- half 1 (K 64..127) ----
        CP_ASYNC_WAIT1();
        __syncthreads();
#pragma unroll
        for (int ks = 0; ks < 4; ks++) {
            const uint32_t koff = ks * 32;
            const uint32_t kb   = 128 + ks * 32;
            uint32_t ah[2][4], al[2][4], bhf[2][4], blf[2][4];
            ldm_x4(ah[0], a1Hi + koff);
            ldm_x4(ah[1], a1Hi + 16 * PITCH_A + koff);
            ldm_x4(al[0], a1Lo + koff);
            ldm_x4(al[1], a1Lo + 16 * PITCH_A + koff);
            ldm_x4(bhf[0], bHi + kb);
            ldm_x4(bhf[1], bHi + 16 * PITCH_B + kb);
            ldm_x4(blf[0], bLo + kb);
            ldm_x4(blf[1], bLo + 16 * PITCH_B + kb);
#pragma unroll
            for (int mt = 0; mt < 2; mt++)
#pragma unroll
                for (int nt = 0; nt < 4; nt++) {
                    const uint32_t* b2h = &bhf[nt >> 1][(nt & 1) * 2];
                    const uint32_t* b2l = &blf[nt >> 1][(nt & 1) * 2];
                    mma_bf16(acc[mt][nt], ah[mt], b2h);
                    mma_bf16(acc[mt][nt], al[mt], b2h);
                    mma_bf16(acc[mt][nt], ah[mt], b2l);
                }
        }
        __syncthreads();                       // all warps done reading A1
        if (next < TILES) load_a_half(sb, next, 1, t);
        CP_ASYNC_COMMIT();

        // ---- epilogue (overlaps next-tile loads) ----
        const int row0 = tile * TILE_M;
#pragma unroll
        for (int mt = 0; mt < 2; mt++) {
#pragma unroll
            for (int half = 0; half < 2; half++) {
                int row = row0 + wm * 32 + mt * 16 + g + half * 8;
                if (row >= ROWS) continue;
                int pos = row % POS;
                int k4 = pos % W_DIM;
                int q1 = pos / W_DIM;
                int k3 = q1 % W_DIM;
                int q2 = q1 / W_DIM;
                int k2 = q2 % W_DIM;
                int k1 = q2 / W_DIM;
                int idx = (((k1 & 3) * 4 + (k2 & 3)) * 4 + (k3 & 3)) * 4 + (k4 & 3);
                const float* nkrow = g_nk + idx * M_DIM;
                float* orow = out + (long long)row * M_DIM;
#pragma unroll
                for (int nt = 0; nt < 4; nt++) {
                    int c0 = wn * 32 + nt * 8 + cq;
                    float2 nk = __ldg((const float2*)(nkrow + c0));
                    float2 o;
                    o.x = nk.x - acc[mt][nt][half * 2 + 0];
                    o.y = nk.y - acc[mt][nt][half * 2 + 1];
                    *(float2*)(orow + c0) = o;
                }
            }
        }
    }
}

// ---------------------------------------------------------------------------
extern "C" void kernel_launch(void* const* d_in, const int* in_sizes, int n_in,
                              void* d_out, int out_size) {
    const float* vec    = (const float*)d_in[0];   // (4,16,16,16,16,128)
    const float* Mmat   = (const float*)d_in[1];   // (128,128)
    const float* Acoeff = (const float*)d_in[2];   // (128,256)
    const float* Bbasis = (const float*)d_in[3];   // (256,128)
    float* out = (float*)d_out;                    // (4, 50625, 128)

    cudaFuncSetAttribute(gemm_kernel,
                         cudaFuncAttributeMaxDynamicSharedMemorySize,
                         SMEM_TOTAL);

    pool_kernel<<<TILES, 256>>>((const float4*)vec, Acoeff, Bbasis, Mmat);
    gemm_kernel<<<GRID_GEMM, 256, SMEM_TOTAL>>>(out);
}

// round 10
// speedup vs baseline: 1.8558x; 1.0590x over previous
#include <cuda_runtime.h>
#include <cuda_bf16.h>
#include <cstdint>

#define M_DIM 128
#define D_DIM 16
#define W_DIM 15
#define POS   (W_DIM*W_DIM*W_DIM*W_DIM)   // 50625
#define BATCH 4
#define ROWS  (BATCH*POS)                  // 202500
#define TILE_M 64
#define TILES ((ROWS + TILE_M - 1) / TILE_M)   // 3165
#define PADROWS (TILES * TILE_M)               // 202560
#define GRID_GEMM 444                          // 3 CTAs/SM persistent

// Allocation-free scratch (__device__ globals)
__device__ float         g_nk[256 * M_DIM];
__device__ __nv_bfloat16 g_Eh[M_DIM * M_DIM];             // bf16(M - I)
__device__ __nv_bfloat16 g_Ah[(size_t)PADROWS * M_DIM];   // pooled hi
__device__ __nv_bfloat16 g_Al[(size_t)PADROWS * M_DIM];   // pooled lo

// ---------------------------------------------------------------------------
__device__ __forceinline__ uint32_t smem_u32(const void* p) {
    uint32_t a;
    asm("{ .reg .u64 t; cvta.to.shared.u64 t, %1; cvt.u32.u64 %0, t; }"
        : "=r"(a) : "l"(p));
    return a;
}
__device__ __forceinline__ uint32_t pack_bf16(__nv_bfloat16 a, __nv_bfloat16 b) {
    return ((uint32_t)__bfloat16_as_ushort(b) << 16) | __bfloat16_as_ushort(a);
}
__device__ __forceinline__ void split2(float x, float y, uint32_t& hi, uint32_t& lo) {
    __nv_bfloat16 hx = __float2bfloat16_rn(x);
    __nv_bfloat16 hy = __float2bfloat16_rn(y);
    __nv_bfloat16 lx = __float2bfloat16_rn(x - __bfloat162float(hx));
    __nv_bfloat16 ly = __float2bfloat16_rn(y - __bfloat162float(hy));
    hi = pack_bf16(hx, hy);
    lo = pack_bf16(lx, ly);
}
__device__ __forceinline__ float2 bf16x2_to_f2(uint32_t v) {
    __nv_bfloat162 b;
    *(uint32_t*)&b = v;
    return __bfloat1622float2(b);
}
__device__ __forceinline__ void mma_bf16(float* c, const uint32_t* a, const uint32_t* b) {
    asm volatile(
        "mma.sync.aligned.m16n8k16.row.col.f32.bf16.bf16.f32 "
        "{%0,%1,%2,%3}, {%4,%5,%6,%7}, {%8,%9}, {%0,%1,%2,%3};"
        : "+f"(c[0]), "+f"(c[1]), "+f"(c[2]), "+f"(c[3])
        : "r"(a[0]), "r"(a[1]), "r"(a[2]), "r"(a[3]), "r"(b[0]), "r"(b[1]));
}
__device__ __forceinline__ void ldm_x4(uint32_t (&r)[4], uint32_t addr) {
    asm volatile("ldmatrix.sync.aligned.m8n8.x4.shared.b16 {%0,%1,%2,%3}, [%4];"
        : "=r"(r[0]), "=r"(r[1]), "=r"(r[2]), "=r"(r[3]) : "r"(addr));
}
#define CP_ASYNC_CG(dst, src) \
    asm volatile("cp.async.cg.shared.global [%0], [%1], 16;" \
                 :: "r"(dst), "l"(src) : "memory")
#define CP_ASYNC_COMMIT() asm volatile("cp.async.commit_group;" ::: "memory")
#define CP_ASYNC_WAIT1()  asm volatile("cp.async.wait_group 1;" ::: "memory")

// ---------------------------------------------------------------------------
// Pool (round-7 proven form + folded prep): warp = 8-row chunk, lane = 16B
// channel chunk; run-streaming within the chunk. Blocks 0..191 also build
// the Nk table and E = bf16(M - I).
// ---------------------------------------------------------------------------
__global__ void __launch_bounds__(256)
pool_kernel(const float4* __restrict__ vec,
            const float* __restrict__ Acoeff,
            const float* __restrict__ Bbasis,
            const float* __restrict__ Mmat) {
    const int t = threadIdx.x;

    if (blockIdx.x < 192) {
        int e = blockIdx.x * 256 + t;
        if (e < 32768) {
            int idx = e >> 7, j = e & 127;
            g_nk[e] = Acoeff[j * 256 + idx] * Bbasis[idx * M_DIM + j];
        } else {
            int e2 = e - 32768;                    // 0..16383
            int r = e2 >> 7, c = e2 & 127;
            float v = Mmat[e2] - (r == c ? 1.0f : 0.0f);
            g_Eh[e2] = __float2bfloat16_rn(v);
        }
    }

    const int lane = t & 31;
    const int sub  = t >> 5;
    const int q    = lane;
    int r    = blockIdx.x * 64 + sub * 8;
    int rend = r + 8;

    // zero any padded rows
    for (int rr = (r < ROWS ? ROWS : r); rr < rend; rr++) {
        uint2 z = make_uint2(0u, 0u);
        ((uint2*)g_Ah)[(size_t)rr * 32 + q] = z;
        ((uint2*)g_Al)[(size_t)rr * 32 + q] = z;
    }
    int gend = rend < ROWS ? rend : ROWS;

    const int S4 = 32, S3 = 512, S2 = 8192, S1 = 131072;  // float4 strides
    const long long SBATCH = (long long)S1 * D_DIM;

    while (r < gend) {
        int b   = r / POS;
        int pos = r - b * POS;
        int k4  = pos % W_DIM;
        int r1  = pos / W_DIM;
        int k3  = r1 % W_DIM;
        int r2  = r1 / W_DIM;
        int k2  = r2 % W_DIM;
        int k1  = r2 / W_DIM;
        int segend = r + (W_DIM - k4);
        if (segend > gend) segend = gend;
        const int L = segend - r;

        const float4* p = vec + b * SBATCH + k1 * S1 + k2 * S2
                              + k3 * S3 + k4 * S4 + q;
        const int co1 = S3, co2 = S2, co3 = S2 + S3;
        const int co4 = S1, co5 = S1 + S3, co6 = S1 + S2, co7 = S1 + S2 + S3;

        float4 sp;
        {
            float sx = 0.f, sy = 0.f, sz = 0.f, sw = 0.f;
            float4 v;
            v = __ldg(p);        sx += v.x; sy += v.y; sz += v.z; sw += v.w;
            v = __ldg(p + co1);  sx += v.x; sy += v.y; sz += v.z; sw += v.w;
            v = __ldg(p + co2);  sx += v.x; sy += v.y; sz += v.z; sw += v.w;
            v = __ldg(p + co3);  sx += v.x; sy += v.y; sz += v.z; sw += v.w;
            v = __ldg(p + co4);  sx += v.x; sy += v.y; sz += v.z; sw += v.w;
            v = __ldg(p + co5);  sx += v.x; sy += v.y; sz += v.z; sw += v.w;
            v = __ldg(p + co6);  sx += v.x; sy += v.y; sz += v.z; sw += v.w;
            v = __ldg(p + co7);  sx += v.x; sy += v.y; sz += v.z; sw += v.w;
            sp = make_float4(sx, sy, sz, sw);
        }
        for (int j = 1; j <= L; j++) {
            const float4* pj = p + j * S4;
            float sx = 0.f, sy = 0.f, sz = 0.f, sw = 0.f;
            float4 v;
            v = __ldg(pj);       sx += v.x; sy += v.y; sz += v.z; sw += v.w;
            v = __ldg(pj + co1); sx += v.x; sy += v.y; sz += v.z; sw += v.w;
            v = __ldg(pj + co2); sx += v.x; sy += v.y; sz += v.z; sw += v.w;
            v = __ldg(pj + co3); sx += v.x; sy += v.y; sz += v.z; sw += v.w;
            v = __ldg(pj + co4); sx += v.x; sy += v.y; sz += v.z; sw += v.w;
            v = __ldg(pj + co5); sx += v.x; sy += v.y; sz += v.z; sw += v.w;
            v = __ldg(pj + co6); sx += v.x; sy += v.y; sz += v.z; sw += v.w;
            v = __ldg(pj + co7); sx += v.x; sy += v.y; sz += v.z; sw += v.w;

            float ox = (sp.x + sx) * 0.0625f;
            float oy = (sp.y + sy) * 0.0625f;
            float oz = (sp.z + sz) * 0.0625f;
            float ow = (sp.w + sw) * 0.0625f;
            sp = make_float4(sx, sy, sz, sw);

            uint2 hv, lv;
            split2(ox, oy, hv.x, lv.x);
            split2(oz, ow, hv.y, lv.y);
            size_t orow = (size_t)(r + j - 1) * 32 + q;
            ((uint2*)g_Ah)[orow] = hv;
            ((uint2*)g_Al)[orow] = lv;
        }
        r = segend;
    }
}

// ---------------------------------------------------------------------------
// Persistent GEMM (round-7 proven pipeline): acc = A_hi @ E^T (1 bf16 pass);
// out = Nk - (A_hi + A_lo from gmem) - acc. E loaded once/CTA; A_hi K-halves
// in fixed slots A0/A1, next-tile loads issued after post-MMA syncthreads.
// Epilogue never touches A smem.
// ---------------------------------------------------------------------------
#define PITCH_B   272
#define PITCH_A   144
#define OFF_E     0
#define OFF_A0    (128 * PITCH_B)             // 34816
#define OFF_A1    (OFF_A0 + TILE_M * PITCH_A) // 44032
#define SMEM_TOTAL (OFF_A1 + TILE_M * PITCH_A) // 53248

// Load K-half h of tile's A_hi into its fixed slot (512 x 16B chunks)
__device__ __forceinline__ void load_a_half(uint32_t sb, int tile, int h, int t) {
    const uint32_t base = (h ? OFF_A1 : OFF_A0);
    const char* ah = (const char*)g_Ah;
    const size_t rowbase = (size_t)tile * TILE_M;
#pragma unroll
    for (int i = 0; i < 2; i++) {
        int e = t + i * 256;            // 0..511
        int r = e >> 3, c = e & 7;      // row 0..63, 16B chunk 0..7
        uint32_t dst = sb + base + (uint32_t)(r * PITCH_A + c * 16);
        size_t src = (rowbase + r) * 256 + (size_t)h * 128 + c * 16;
        CP_ASYNC_CG(dst, ah + src);
    }
}

__global__ void __launch_bounds__(256, 3)
gemm_kernel(float* __restrict__ out) {
    extern __shared__ char smem[];
    const uint32_t sb = smem_u32(smem);
    const int t    = threadIdx.x;
    const int wid  = t >> 5;
    const int lane = t & 31;
    const int wm = wid & 1;
    const int wn = wid >> 1;

    int tile = blockIdx.x;
    {   // prologue: E (once) + first tile's A halves
        const char* eh = (const char*)g_Eh;
#pragma unroll
        for (int i = 0; i < 8; i++) {                  // 2048 chunks
            int e = t + i * 256;
            int r = e >> 4, c = e & 15;
            CP_ASYNC_CG(sb + OFF_E + (uint32_t)(r * PITCH_B + c * 16),
                        eh + r * 256 + c * 16);
        }
        load_a_half(sb, tile, 0, t);
        CP_ASYNC_COMMIT();                             // G: E + A0(t0)
        load_a_half(sb, tile, 1, t);
        CP_ASYNC_COMMIT();                             // G: A1(t0)
    }

    const uint32_t eHi = sb + OFF_E
        + (uint32_t)((wn * 32 + (lane & 7) + (lane >> 4) * 8) * PITCH_B
                     + ((lane >> 3) & 1) * 16);
    const uint32_t a0Frag = sb + OFF_A0
        + (uint32_t)((wm * 32 + (lane & 15)) * PITCH_A + (lane >> 4) * 16);
    const uint32_t a1Frag = a0Frag + (OFF_A1 - OFF_A0);

    const int g  = lane >> 2;
    const int cq = (lane & 3) * 2;

    const char* ahB = (const char*)g_Ah;
    const char* alB = (const char*)g_Al;

    for (; tile < TILES; tile += GRID_GEMM) {
        const int next = tile + GRID_GEMM;
        float acc[2][4][4];
#pragma unroll
        for (int mt = 0; mt < 2; mt++)
#pragma unroll
            for (int nt = 0; nt < 4; nt++)
#pragma unroll
                for (int i = 0; i < 4; i++) acc[mt][nt][i] = 0.f;

        // ---- half 0 (K 0..63) ----
        CP_ASYNC_WAIT1();
        __syncthreads();
#pragma unroll
        for (int ks = 0; ks < 4; ks++) {
            const uint32_t koff = ks * 32;
            uint32_t ah[2][4], ehf[2][4];
            ldm_x4(ah[0], a0Frag + koff);
            ldm_x4(ah[1], a0Frag + 16 * PITCH_A + koff);
            ldm_x4(ehf[0], eHi + koff);
            ldm_x4(ehf[1], eHi + 16 * PITCH_B + koff);
#pragma unroll
            for (int mt = 0; mt < 2; mt++)
#pragma unroll
                for (int nt = 0; nt < 4; nt++)
                    mma_bf16(acc[mt][nt], ah[mt], &ehf[nt >> 1][(nt & 1) * 2]);
        }
        __syncthreads();                       // all warps done reading A0
        if (next < TILES) load_a_half(sb, next, 0, t);
        CP_ASYNC_COMMIT();

        // ---- half 1 (K 64..127) ----
        CP_ASYNC_WAIT1();
        __syncthreads();
#pragma unroll
        for (int ks = 0; ks < 4; ks++) {
            const uint32_t koff = ks * 32;
            const uint32_t kb   = 128 + ks * 32;
            uint32_t ah[2][4], ehf[2][4];
            ldm_x4(ah[0], a1Frag + koff);
            ldm_x4(ah[1], a1Frag + 16 * PITCH_A + koff);
            ldm_x4(ehf[0], eHi + kb);
            ldm_x4(ehf[1], eHi + 16 * PITCH_B + kb);
#pragma unroll
            for (int mt = 0; mt < 2; mt++)
#pragma unroll
                for (int nt = 0; nt < 4; nt++)
                    mma_bf16(acc[mt][nt], ah[mt], &ehf[nt >> 1][(nt & 1) * 2]);
        }
        __syncthreads();                       // all warps done reading A1
        if (next < TILES) load_a_half(sb, next, 1, t);
        CP_ASYNC_COMMIT();

        // ---- epilogue: out = Nk - (Ahi+Alo) - acc (pooled from gmem) ----
        const int row0 = tile * TILE_M;
#pragma unroll
        for (int mt = 0; mt < 2; mt++) {
#pragma unroll
            for (int h8 = 0; h8 < 2; h8++) {
                int row = row0 + wm * 32 + mt * 16 + g + h8 * 8;
                if (row >= ROWS) continue;
                int pos = row % POS;
                int k4 = pos % W_DIM;
                int q1 = pos / W_DIM;
                int k3 = q1 % W_DIM;
                int q2 = q1 / W_DIM;
                int k2 = q2 % W_DIM;
                int k1 = q2 / W_DIM;
                int idx = (((k1 & 3) * 4 + (k2 & 3)) * 4 + (k3 & 3)) * 4 + (k4 & 3);
                const float* nkrow = g_nk + idx * M_DIM;
                float* orow = out + (long long)row * M_DIM;
                const size_t abyte = (size_t)row * 256;
#pragma unroll
                for (int nt = 0; nt < 4; nt++) {
                    int c0 = wn * 32 + nt * 8 + cq;
                    float2 nk = __ldg((const float2*)(nkrow + c0));
                    float2 ph = bf16x2_to_f2(
                        __ldg((const uint32_t*)(ahB + abyte + c0 * 2)));
                    float2 pl = bf16x2_to_f2(
                        __ldg((const uint32_t*)(alB + abyte + c0 * 2)));
                    float2 o;
                    o.x = nk.x - (ph.x + pl.x) - acc[mt][nt][h8 * 2 + 0];
                    o.y = nk.y - (ph.y + pl.y) - acc[mt][nt][h8 * 2 + 1];
                    *(float2*)(orow + c0) = o;
                }
            }
        }
    }
}

// ---------------------------------------------------------------------------
extern "C" void kernel_launch(void* const* d_in, const int* in_sizes, int n_in,
                              void* d_out, int out_size) {
    const float* vec    = (const float*)d_in[0];   // (4,16,16,16,16,128)
    const float* Mmat   = (const float*)d_in[1];   // (128,128)
    const float* Acoeff = (const float*)d_in[2];   // (128,256)
    const float* Bbasis = (const float*)d_in[3];   // (256,128)
    float* out = (float*)d_out;                    // (4, 50625, 128)

    cudaFuncSetAttribute(gemm_kernel,
                         cudaFuncAttributeMaxDynamicSharedMemorySize,
                         SMEM_TOTAL);

    pool_kernel<<<TILES, 256>>>((const float4*)vec, Acoeff, Bbasis, Mmat);
    gemm_kernel<<<GRID_GEMM, 256, SMEM_TOTAL>>>(out);
}

// round 11
// speedup vs baseline: 2.0765x; 1.1189x over previous
#include <cuda_runtime.h>
#include <cuda_bf16.h>
#include <cstdint>

#define M_DIM 128
#define D_DIM 16
#define W_DIM 15
#define POS   (W_DIM*W_DIM*W_DIM*W_DIM)   // 50625
#define BATCH 4
#define ROWS  (BATCH*POS)                  // 202500
#define TILE_M 64
#define TILES ((ROWS + TILE_M - 1) / TILE_M)   // 3165
#define PADROWS (TILES * TILE_M)               // 202560
#define GRID_GEMM 456                          // 3 CTAs/SM x 152 SMs

// Allocation-free scratch (__device__ globals)
__device__ float         g_nk[256 * M_DIM];
__device__ __nv_bfloat16 g_Eh[M_DIM * M_DIM];             // bf16(M - I)
__device__ __nv_bfloat16 g_Ah[(size_t)PADROWS * M_DIM];   // pooled hi
__device__ __nv_bfloat16 g_Al[(size_t)PADROWS * M_DIM];   // pooled lo

// ---------------------------------------------------------------------------
__device__ __forceinline__ uint32_t smem_u32(const void* p) {
    uint32_t a;
    asm("{ .reg .u64 t; cvta.to.shared.u64 t, %1; cvt.u32.u64 %0, t; }"
        : "=r"(a) : "l"(p));
    return a;
}
__device__ __forceinline__ uint32_t pack_bf16(__nv_bfloat16 a, __nv_bfloat16 b) {
    return ((uint32_t)__bfloat16_as_ushort(b) << 16) | __bfloat16_as_ushort(a);
}
__device__ __forceinline__ void split2(float x, float y, uint32_t& hi, uint32_t& lo) {
    __nv_bfloat16 hx = __float2bfloat16_rn(x);
    __nv_bfloat16 hy = __float2bfloat16_rn(y);
    __nv_bfloat16 lx = __float2bfloat16_rn(x - __bfloat162float(hx));
    __nv_bfloat16 ly = __float2bfloat16_rn(y - __bfloat162float(hy));
    hi = pack_bf16(hx, hy);
    lo = pack_bf16(lx, ly);
}
__device__ __forceinline__ float2 bf16x2_to_f2(uint32_t v) {
    __nv_bfloat162 b;
    *(uint32_t*)&b = v;
    return __bfloat1622float2(b);
}
__device__ __forceinline__ void mma_bf16(float* c, const uint32_t* a, const uint32_t* b) {
    asm volatile(
        "mma.sync.aligned.m16n8k16.row.col.f32.bf16.bf16.f32 "
        "{%0,%1,%2,%3}, {%4,%5,%6,%7}, {%8,%9}, {%0,%1,%2,%3};"
        : "+f"(c[0]), "+f"(c[1]), "+f"(c[2]), "+f"(c[3])
        : "r"(a[0]), "r"(a[1]), "r"(a[2]), "r"(a[3]), "r"(b[0]), "r"(b[1]));
}
__device__ __forceinline__ void ldm_x4(uint32_t (&r)[4], uint32_t addr) {
    asm volatile("ldmatrix.sync.aligned.m8n8.x4.shared.b16 {%0,%1,%2,%3}, [%4];"
        : "=r"(r[0]), "=r"(r[1]), "=r"(r[2]), "=r"(r[3]) : "r"(addr));
}
#define CP_ASYNC_CG(dst, src) \
    asm volatile("cp.async.cg.shared.global [%0], [%1], 16;" \
                 :: "r"(dst), "l"(src) : "memory")
#define CP_ASYNC_COMMIT() asm volatile("cp.async.commit_group;" ::: "memory")
#define CP_ASYNC_WAIT1()  asm volatile("cp.async.wait_group 1;" ::: "memory")

// ---------------------------------------------------------------------------
// Pool (round-7/10 proven form + folded prep): warp = 8-row chunk,
// lane = 16B channel chunk; run-streaming within the chunk.
// Blocks 0..191 also build the Nk table and E = bf16(M - I).
// ---------------------------------------------------------------------------
__global__ void __launch_bounds__(256)
pool_kernel(const float4* __restrict__ vec,
            const float* __restrict__ Acoeff,
            const float* __restrict__ Bbasis,
            const float* __restrict__ Mmat) {
    const int t = threadIdx.x;

    if (blockIdx.x < 192) {
        int e = blockIdx.x * 256 + t;
        if (e < 32768) {
            int idx = e >> 7, j = e & 127;
            g_nk[e] = Acoeff[j * 256 + idx] * Bbasis[idx * M_DIM + j];
        } else {
            int e2 = e - 32768;                    // 0..16383
            int r = e2 >> 7, c = e2 & 127;
            float v = Mmat[e2] - (r == c ? 1.0f : 0.0f);
            g_Eh[e2] = __float2bfloat16_rn(v);
        }
    }

    const int lane = t & 31;
    const int sub  = t >> 5;
    const int q    = lane;
    int r    = blockIdx.x * 64 + sub * 8;
    int rend = r + 8;

    for (int rr = (r < ROWS ? ROWS : r); rr < rend; rr++) {
        uint2 z = make_uint2(0u, 0u);
        ((uint2*)g_Ah)[(size_t)rr * 32 + q] = z;
        ((uint2*)g_Al)[(size_t)rr * 32 + q] = z;
    }
    int gend = rend < ROWS ? rend : ROWS;

    const int S4 = 32, S3 = 512, S2 = 8192, S1 = 131072;  // float4 strides
    const long long SBATCH = (long long)S1 * D_DIM;

    while (r < gend) {
        int b   = r / POS;
        int pos = r - b * POS;
        int k4  = pos % W_DIM;
        int r1  = pos / W_DIM;
        int k3  = r1 % W_DIM;
        int r2  = r1 / W_DIM;
        int k2  = r2 % W_DIM;
        int k1  = r2 / W_DIM;
        int segend = r + (W_DIM - k4);
        if (segend > gend) segend = gend;
        const int L = segend - r;

        const float4* p = vec + b * SBATCH + k1 * S1 + k2 * S2
                              + k3 * S3 + k4 * S4 + q;
        const int co1 = S3, co2 = S2, co3 = S2 + S3;
        const int co4 = S1, co5 = S1 + S3, co6 = S1 + S2, co7 = S1 + S2 + S3;

        float4 sp;
        {
            float sx = 0.f, sy = 0.f, sz = 0.f, sw = 0.f;
            float4 v;
            v = __ldg(p);        sx += v.x; sy += v.y; sz += v.z; sw += v.w;
            v = __ldg(p + co1);  sx += v.x; sy += v.y; sz += v.z; sw += v.w;
            v = __ldg(p + co2);  sx += v.x; sy += v.y; sz += v.z; sw += v.w;
            v = __ldg(p + co3);  sx += v.x; sy += v.y; sz += v.z; sw += v.w;
            v = __ldg(p + co4);  sx += v.x; sy += v.y; sz += v.z; sw += v.w;
            v = __ldg(p + co5);  sx += v.x; sy += v.y; sz += v.z; sw += v.w;
            v = __ldg(p + co6);  sx += v.x; sy += v.y; sz += v.z; sw += v.w;
            v = __ldg(p + co7);  sx += v.x; sy += v.y; sz += v.z; sw += v.w;
            sp = make_float4(sx, sy, sz, sw);
        }
        for (int j = 1; j <= L; j++) {
            const float4* pj = p + j * S4;
            float sx = 0.f, sy = 0.f, sz = 0.f, sw = 0.f;
            float4 v;
            v = __ldg(pj);       sx += v.x; sy += v.y; sz += v.z; sw += v.w;
            v = __ldg(pj + co1); sx += v.x; sy += v.y; sz += v.z; sw += v.w;
            v = __ldg(pj + co2); sx += v.x; sy += v.y; sz += v.z; sw += v.w;
            v = __ldg(pj + co3); sx += v.x; sy += v.y; sz += v.z; sw += v.w;
            v = __ldg(pj + co4); sx += v.x; sy += v.y; sz += v.z; sw += v.w;
            v = __ldg(pj + co5); sx += v.x; sy += v.y; sz += v.z; sw += v.w;
            v = __ldg(pj + co6); sx += v.x; sy += v.y; sz += v.z; sw += v.w;
            v = __ldg(pj + co7); sx += v.x; sy += v.y; sz += v.z; sw += v.w;

            float ox = (sp.x + sx) * 0.0625f;
            float oy = (sp.y + sy) * 0.0625f;
            float oz = (sp.z + sz) * 0.0625f;
            float ow = (sp.w + sw) * 0.0625f;
            sp = make_float4(sx, sy, sz, sw);

            uint2 hv, lv;
            split2(ox, oy, hv.x, lv.x);
            split2(oz, ow, hv.y, lv.y);
            size_t orow = (size_t)(r + j - 1) * 32 + q;
            ((uint2*)g_Ah)[orow] = hv;
            ((uint2*)g_Al)[orow] = lv;
        }
        r = segend;
    }
}

// ---------------------------------------------------------------------------
// Persistent GEMM: acc = A_hi @ E^T (1 bf16 pass); out = Nk - (Ahi+Alo) - acc.
// Round-10 proven pipeline. NEW: epilogue stages fp32 acc in smem (two 32-row
// phases), then does a fully-coalesced gmem pass (lanes cover whole rows).
// ---------------------------------------------------------------------------
#define PITCH_B   272
#define PITCH_A   144
#define PITCH_ST  132                          // fp32 words per staged row
#define OFF_E     0
#define OFF_A0    (128 * PITCH_B)              // 34816
#define OFF_A1    (OFF_A0 + TILE_M * PITCH_A)  // 44032
#define OFF_ST    (OFF_A1 + TILE_M * PITCH_A)  // 53248
#define SMEM_TOTAL (OFF_ST + 32 * PITCH_ST * 4) // 70144

__device__ __forceinline__ void load_a_half(uint32_t sb, int tile, int h, int t) {
    const uint32_t base = (h ? OFF_A1 : OFF_A0);
    const char* ah = (const char*)g_Ah;
    const size_t rowbase = (size_t)tile * TILE_M;
#pragma unroll
    for (int i = 0; i < 2; i++) {
        int e = t + i * 256;            // 0..511
        int r = e >> 3, c = e & 7;      // row 0..63, 16B chunk 0..7
        uint32_t dst = sb + base + (uint32_t)(r * PITCH_A + c * 16);
        size_t src = (rowbase + r) * 256 + (size_t)h * 128 + c * 16;
        CP_ASYNC_CG(dst, ah + src);
    }
}

__global__ void __launch_bounds__(256, 3)
gemm_kernel(float* __restrict__ out) {
    extern __shared__ char smem[];
    const uint32_t sb = smem_u32(smem);
    const int t    = threadIdx.x;
    const int wid  = t >> 5;
    const int lane = t & 31;
    const int wm = wid & 1;
    const int wn = wid >> 1;

    int tile = blockIdx.x;
    {   // prologue: E (once) + first tile's A halves
        const char* eh = (const char*)g_Eh;
#pragma unroll
        for (int i = 0; i < 8; i++) {                  // 2048 chunks
            int e = t + i * 256;
            int r = e >> 4, c = e & 15;
            CP_ASYNC_CG(sb + OFF_E + (uint32_t)(r * PITCH_B + c * 16),
                        eh + r * 256 + c * 16);
        }
        load_a_half(sb, tile, 0, t);
        CP_ASYNC_COMMIT();                             // G: E + A0(t0)
        load_a_half(sb, tile, 1, t);
        CP_ASYNC_COMMIT();                             // G: A1(t0)
    }

    const uint32_t eHi = sb + OFF_E
        + (uint32_t)((wn * 32 + (lane & 7) + (lane >> 4) * 8) * PITCH_B
                     + ((lane >> 3) & 1) * 16);
    const uint32_t a0Frag = sb + OFF_A0
        + (uint32_t)((wm * 32 + (lane & 15)) * PITCH_A + (lane >> 4) * 16);
    const uint32_t a1Frag = a0Frag + (OFF_A1 - OFF_A0);

    const int g  = lane >> 2;
    const int cq = (lane & 3) * 2;

    const char* ahB = (const char*)g_Ah;
    const char* alB = (const char*)g_Al;

    for (; tile < TILES; tile += GRID_GEMM) {
        const int next = tile + GRID_GEMM;
        float acc[2][4][4];
#pragma unroll
        for (int mt = 0; mt < 2; mt++)
#pragma unroll
            for (int nt = 0; nt < 4; nt++)
#pragma unroll
                for (int i = 0; i < 4; i++) acc[mt][nt][i] = 0.f;

        // ---- half 0 (K 0..63) ----
        CP_ASYNC_WAIT1();
        __syncthreads();
#pragma unroll
        for (int ks = 0; ks < 4; ks++) {
            const uint32_t koff = ks * 32;
            uint32_t ah[2][4], ehf[2][4];
            ldm_x4(ah[0], a0Frag + koff);
            ldm_x4(ah[1], a0Frag + 16 * PITCH_A + koff);
            ldm_x4(ehf[0], eHi + koff);
            ldm_x4(ehf[1], eHi + 16 * PITCH_B + koff);
#pragma unroll
            for (int mt = 0; mt < 2; mt++)
#pragma unroll
                for (int nt = 0; nt < 4; nt++)
                    mma_bf16(acc[mt][nt], ah[mt], &ehf[nt >> 1][(nt & 1) * 2]);
        }
        __syncthreads();                       // all warps done reading A0
        if (next < TILES) load_a_half(sb, next, 0, t);
        CP_ASYNC_COMMIT();

        // ---- half 1 (K 64..127) ----
        CP_ASYNC_WAIT1();
        __syncthreads();
#pragma unroll
        for (int ks = 0; ks < 4; ks++) {
            const uint32_t koff = ks * 32;
            const uint32_t kb   = 128 + ks * 32;
            uint32_t ah[2][4], ehf[2][4];
            ldm_x4(ah[0], a1Frag + koff);
            ldm_x4(ah[1], a1Frag + 16 * PITCH_A + koff);
            ldm_x4(ehf[0], eHi + kb);
            ldm_x4(ehf[1], eHi + 16 * PITCH_B + kb);
#pragma unroll
            for (int mt = 0; mt < 2; mt++)
#pragma unroll
                for (int nt = 0; nt < 4; nt++)
                    mma_bf16(acc[mt][nt], ah[mt], &ehf[nt >> 1][(nt & 1) * 2]);
        }
        __syncthreads();                       // all warps done reading A1
        if (next < TILES) load_a_half(sb, next, 1, t);
        CP_ASYNC_COMMIT();

        // ---- epilogue: two 32-row phases. Stage fp32 acc in smem, then a
        //      coalesced pass: out = Nk - (Ahi+Alo) - acc. ----
        const int row0 = tile * TILE_M;
#pragma unroll
        for (int phase = 0; phase < 2; phase++) {
            if (wm == phase) {                 // stage this warp's rows
#pragma unroll
                for (int mt = 0; mt < 2; mt++)
#pragma unroll
                    for (int h8 = 0; h8 < 2; h8++) {
                        int br = mt * 16 + g + h8 * 8;   // 0..31 buffer row
#pragma unroll
                        for (int nt = 0; nt < 4; nt++) {
                            float2 v;
                            v.x = acc[mt][nt][h8 * 2 + 0];
                            v.y = acc[mt][nt][h8 * 2 + 1];
                            *(float2*)(smem + OFF_ST
                                + (br * PITCH_ST + wn * 32 + nt * 8 + cq) * 4) = v;
                        }
                    }
            }
            __syncthreads();
            // coalesced pass over 32 rows x 16 chunks (8 cols each)
#pragma unroll
            for (int i = 0; i < 2; i++) {
                int e = t + i * 256;           // 0..511
                int r32 = e >> 4, c = e & 15;
                int row = row0 + phase * 32 + r32;
                if (row < ROWS) {
                    int pos = row % POS;
                    int k4 = pos % W_DIM;
                    int q1 = pos / W_DIM;
                    int k3 = q1 % W_DIM;
                    int q2 = q1 / W_DIM;
                    int k2 = q2 % W_DIM;
                    int k1 = q2 / W_DIM;
                    int idx = (((k1 & 3) * 4 + (k2 & 3)) * 4 + (k3 & 3)) * 4
                              + (k4 & 3);
                    const float* nkp = g_nk + idx * M_DIM + c * 8;
                    float4 nk0 = __ldg((const float4*)nkp);
                    float4 nk1 = __ldg((const float4*)(nkp + 4));
                    uint4 ph = __ldg((const uint4*)(ahB + (size_t)row * 256 + c * 16));
                    uint4 pl = __ldg((const uint4*)(alB + (size_t)row * 256 + c * 16));
                    const float* st = (const float*)(smem + OFF_ST
                                        + (r32 * PITCH_ST + c * 8) * 4);
                    float2 h0 = bf16x2_to_f2(ph.x), l0 = bf16x2_to_f2(pl.x);
                    float2 h1 = bf16x2_to_f2(ph.y), l1 = bf16x2_to_f2(pl.y);
                    float2 h2 = bf16x2_to_f2(ph.z), l2 = bf16x2_to_f2(pl.z);
                    float2 h3 = bf16x2_to_f2(ph.w), l3 = bf16x2_to_f2(pl.w);
                    float4 o0, o1;
                    o0.x = nk0.x - (h0.x + l0.x) - st[0];
                    o0.y = nk0.y - (h0.y + l0.y) - st[1];
                    o0.z = nk0.z - (h1.x + l1.x) - st[2];
                    o0.w = nk0.w - (h1.y + l1.y) - st[3];
                    o1.x = nk1.x - (h2.x + l2.x) - st[4];
                    o1.y = nk1.y - (h2.y + l2.y) - st[5];
                    o1.z = nk1.z - (h3.x + l3.x) - st[6];
                    o1.w = nk1.w - (h3.y + l3.y) - st[7];
                    float* op = out + (size_t)row * M_DIM + c * 8;
                    *(float4*)op = o0;
                    *(float4*)(op + 4) = o1;
                }
            }
            __syncthreads();                   // buffer reuse by next phase
        }
    }
}

// ---------------------------------------------------------------------------
extern "C" void kernel_launch(void* const* d_in, const int* in_sizes, int n_in,
                              void* d_out, int out_size) {
    const float* vec    = (const float*)d_in[0];   // (4,16,16,16,16,128)
    const float* Mmat   = (const float*)d_in[1];   // (128,128)
    const float* Acoeff = (const float*)d_in[2];   // (128,256)
    const float* Bbasis = (const float*)d_in[3];   // (256,128)
    float* out = (float*)d_out;                    // (4, 50625, 128)

    cudaFuncSetAttribute(gemm_kernel,
                         cudaFuncAttributeMaxDynamicSharedMemorySize,
                         SMEM_TOTAL);

    pool_kernel<<<TILES, 256>>>((const float4*)vec, Acoeff, Bbasis, Mmat);
    gemm_kernel<<<GRID_GEMM, 256, SMEM_TOTAL>>>(out);
}